// round 6
// baseline (speedup 1.0000x reference)
#include <cuda_runtime.h>
#include <cuda_bf16.h>
#include <cstdint>
#include <math.h>

// ---------------------------------------------------------------------------
// SimpleTransformerBlock via warp-level bf16 mma.sync (sm_103 non-'a' PTX
// target: no tcgen05). fp32 accuracy via bf16 hi/lo split:
// A = [hi|hi|lo], B = [hi|lo|hi], K' = 3K.
// R6: 128x256 CTA tile, 64x64 warp tile (MMA:LDSM 4.0), 3-stage cp.async.
// ---------------------------------------------------------------------------

#define M_ROWS 16384

// fp32 scratch
__device__ float g_qkv [(size_t)M_ROWS * 3072];
__device__ float g_x1  [(size_t)M_ROWS * 1024];
// bf16 split scratch
__device__ __nv_bfloat16 g_act  [(size_t)M_ROWS * 3072];     // A split, K=1024
__device__ __nv_bfloat16 g_amlp [(size_t)M_ROWS * 12288];    // A split, K=4096
__device__ __nv_bfloat16 g_ws_qkv [(size_t)3072 * 3072];
__device__ __nv_bfloat16 g_ws_proj[(size_t)1024 * 3072];
__device__ __nv_bfloat16 g_ws_w1  [(size_t)4096 * 3072];
__device__ __nv_bfloat16 g_ws_w2  [(size_t)1024 * 12288];

// ---------------------------------------------------------------------------
// PTX wrappers
// ---------------------------------------------------------------------------
__device__ __forceinline__ uint32_t smem_u32(const void* p) {
    uint32_t a;
    asm("{ .reg .u64 t; cvta.to.shared.u64 t, %1; cvt.u32.u64 %0, t; }" : "=r"(a) : "l"(p));
    return a;
}
__device__ __forceinline__ void cp_async16(uint32_t dst, const void* src) {
    asm volatile("cp.async.cg.shared.global [%0], [%1], 16;" :: "r"(dst), "l"(src));
}
__device__ __forceinline__ void cp_commit() {
    asm volatile("cp.async.commit_group;" ::: "memory");
}
__device__ __forceinline__ void cp_wait1() {
    asm volatile("cp.async.wait_group 1;" ::: "memory");
}
__device__ __forceinline__ void ldsm_x4(uint32_t* r, uint32_t addr) {
    asm volatile("ldmatrix.sync.aligned.m8n8.x4.shared.b16 {%0,%1,%2,%3}, [%4];"
                 : "=r"(r[0]), "=r"(r[1]), "=r"(r[2]), "=r"(r[3]) : "r"(addr));
}
__device__ __forceinline__ void mma16816(float* c, const uint32_t* a, uint32_t b0, uint32_t b1) {
    asm volatile(
        "mma.sync.aligned.m16n8k16.row.col.f32.bf16.bf16.f32 "
        "{%0,%1,%2,%3}, {%4,%5,%6,%7}, {%8,%9}, {%0,%1,%2,%3};"
        : "+f"(c[0]), "+f"(c[1]), "+f"(c[2]), "+f"(c[3])
        : "r"(a[0]), "r"(a[1]), "r"(a[2]), "r"(a[3]), "r"(b0), "r"(b1));
}
__device__ __forceinline__ uint32_t pack_bf16x2(float x, float y) {
    __nv_bfloat162 h = __floats2bfloat162_rn(x, y);
    return *(uint32_t*)&h;
}
__device__ __forceinline__ void split_pair(float x, float y, uint32_t& hi, uint32_t& lo) {
    __nv_bfloat16 hx = __float2bfloat16(x), hy = __float2bfloat16(y);
    hi = ((uint32_t)*(uint16_t*)&hy << 16) | *(uint16_t*)&hx;
    lo = pack_bf16x2(x - __bfloat162float(hx), y - __bfloat162float(hy));
}

// ---------------------------------------------------------------------------
// LayerNorm fused with hi/lo split: out row = [hi(1024) | hi(1024) | lo(1024)]
// ---------------------------------------------------------------------------
__global__ __launch_bounds__(256) void ln_split_kernel(
    const float* __restrict__ x, const float* __restrict__ w,
    const float* __restrict__ b, __nv_bfloat16* __restrict__ out)
{
    const int row = blockIdx.x;
    const int t   = threadIdx.x;
    const float4 v = ((const float4*)(x + (size_t)row * 1024))[t];
    float s  = v.x + v.y + v.z + v.w;
    float sq = v.x*v.x + v.y*v.y + v.z*v.z + v.w*v.w;
    #pragma unroll
    for (int o = 16; o > 0; o >>= 1) {
        s  += __shfl_xor_sync(0xffffffffu, s,  o);
        sq += __shfl_xor_sync(0xffffffffu, sq, o);
    }
    __shared__ float sm[8], sm2[8];
    const int warp = t >> 5, lane = t & 31;
    if (lane == 0) { sm[warp] = s; sm2[warp] = sq; }
    __syncthreads();
    if (t == 0) {
        float a = 0.f, c = 0.f;
        #pragma unroll
        for (int i = 0; i < 8; i++) { a += sm[i]; c += sm2[i]; }
        sm[0] = a; sm2[0] = c;
    }
    __syncthreads();
    const float mean = sm[0]  * (1.f / 1024.f);
    const float var  = sm2[0] * (1.f / 1024.f) - mean * mean;
    const float inv  = rsqrtf(var + 1e-5f);
    const float4 wv = ((const float4*)w)[t];
    const float4 bv = ((const float4*)b)[t];
    const float o0 = (v.x - mean) * inv * wv.x + bv.x;
    const float o1 = (v.y - mean) * inv * wv.y + bv.y;
    const float o2 = (v.z - mean) * inv * wv.z + bv.z;
    const float o3 = (v.w - mean) * inv * wv.w + bv.w;

    uint2 H, L;
    split_pair(o0, o1, H.x, L.x);
    split_pair(o2, o3, H.y, L.y);

    __nv_bfloat16* base = out + (size_t)row * 3072 + t * 4;
    *(uint2*)(base)        = H;
    *(uint2*)(base + 1024) = H;
    *(uint2*)(base + 2048) = L;
}

// ---------------------------------------------------------------------------
// fp32 -> bf16 hi/lo split for weights: [hi | lo | hi]
// ---------------------------------------------------------------------------
__global__ __launch_bounds__(256) void split_w_kernel(
    const float* __restrict__ in, __nv_bfloat16* __restrict__ out, int K)
{
    const size_t e = ((size_t)blockIdx.x * 256 + threadIdx.x) * 4;
    const size_t r = e / (size_t)K;
    const int    c = (int)(e - r * (size_t)K);
    const float4 v = *(const float4*)(in + e);

    uint2 H, L;
    split_pair(v.x, v.y, H.x, L.x);
    split_pair(v.z, v.w, H.y, L.y);

    __nv_bfloat16* base = out + r * (size_t)(3 * K) + c;
    *(uint2*)(base)         = H;
    *(uint2*)(base + K)     = L;
    *(uint2*)(base + 2 * K) = H;
}

// ---------------------------------------------------------------------------
// Per-position head-mix attention, float4 LDS, fused hi/lo split output.
// ---------------------------------------------------------------------------
__global__ __launch_bounds__(128) void attn_split_kernel(
    const float* __restrict__ qkv, __nv_bfloat16* __restrict__ out)
{
    const int pos = blockIdx.x;
    const int t   = threadIdx.x;
    const float4* base = (const float4*)(qkv + (size_t)pos * 3072);

    __shared__ float4 sq[256], sk[256], sv[256];
    __shared__ float S[16][17];

    sq[t]       = base[t];
    sq[t + 128] = base[t + 128];
    sk[t]       = base[256 + t];
    sk[t + 128] = base[256 + t + 128];
    sv[t]       = base[512 + t];
    sv[t + 128] = base[512 + t + 128];
    __syncthreads();

    #pragma unroll
    for (int ee = 0; ee < 2; ee++) {
        const int e = t + ee * 128;
        const int h = e >> 4, g = e & 15;
        float4 a = make_float4(0.f, 0.f, 0.f, 0.f);
        #pragma unroll
        for (int d4 = 0; d4 < 16; d4++) {
            const float4 qv = sq[h * 16 + d4];
            const float4 kv = sk[g * 16 + d4];
            a.x = fmaf(qv.x, kv.x, a.x);
            a.y = fmaf(qv.y, kv.y, a.y);
            a.z = fmaf(qv.z, kv.z, a.z);
            a.w = fmaf(qv.w, kv.w, a.w);
        }
        S[h][g] = (a.x + a.y + a.z + a.w) * 0.125f;
    }
    __syncthreads();

    if (t < 16) {
        float m = -1e30f;
        #pragma unroll
        for (int g = 0; g < 16; g++) m = fmaxf(m, S[t][g]);
        float sum = 0.f;
        #pragma unroll
        for (int g = 0; g < 16; g++) { float e = expf(S[t][g] - m); S[t][g] = e; sum += e; }
        const float inv = 1.f / sum;
        #pragma unroll
        for (int g = 0; g < 16; g++) S[t][g] *= inv;
    }
    __syncthreads();

    __nv_bfloat16* orow = out + (size_t)pos * 3072;
    #pragma unroll
    for (int qq = 0; qq < 2; qq++) {
        const int q  = t + qq * 128;
        const int h  = q >> 4, d4 = q & 15;
        float4 a = make_float4(0.f, 0.f, 0.f, 0.f);
        #pragma unroll
        for (int g = 0; g < 16; g++) {
            const float p = S[h][g];
            const float4 vv = sv[g * 16 + d4];
            a.x = fmaf(p, vv.x, a.x);
            a.y = fmaf(p, vv.y, a.y);
            a.z = fmaf(p, vv.z, a.z);
            a.w = fmaf(p, vv.w, a.w);
        }
        uint2 H, L;
        split_pair(a.x, a.y, H.x, L.x);
        split_pair(a.z, a.w, H.y, L.y);
        __nv_bfloat16* p0 = orow + q * 4;
        *(uint2*)(p0)        = H;
        *(uint2*)(p0 + 1024) = H;
        *(uint2*)(p0 + 2048) = L;
    }
}

// ---------------------------------------------------------------------------
// bf16 mma.sync GEMM: C = A[M,K3] @ B[N,K3]^T + bias (+res | +gelu[+split])
// BM=128, BN=256, BK=64, 256 thr (8 warps 2x4, warp tile 64x64),
// 3-stage cp.async pipeline. A: 16KB/stage, B: 32KB/stage (48KB stages).
// Swizzle identity: swz(r*128 + c*16) = r*128 + (c*16 ^ ((r&7)<<4)).
// ---------------------------------------------------------------------------
#define STAGES 3
#define STAGE_BYTES 49152

#define EPI_BIAS 0
#define EPI_RES  1
#define EPI_GELU 2

__device__ __forceinline__ float gelu_exact(float v) {
    return 0.5f * v * (1.0f + erff(v * 0.70710678118654752f));
}

template<int EPI, bool SPLIT_OUT>
__global__ __launch_bounds__(256) void gemm_mma(
    int M, int N, int K3,
    const __nv_bfloat16* __restrict__ A,   // [M, K3]
    const __nv_bfloat16* __restrict__ B,   // [N, K3]
    const float* __restrict__ bias,
    const float* __restrict__ res,
    float* __restrict__ C,
    __nv_bfloat16* __restrict__ Cs)        // split out [hi|hi|lo], stride 3N
{
    extern __shared__ char smem[];
    const uint32_t sbase = smem_u32(smem);

    const int tid  = threadIdx.x;
    const int wid  = tid >> 5;
    const int lane = tid & 31;
    const int wm   = wid & 1;          // m offset 64*wm
    const int wn   = wid >> 1;         // n offset 64*wn

    const int bm = blockIdx.y * 128;
    const int bn = blockIdx.x * 256;

    // ---- loader invariants ------------------------------------------------
    const int l_c8   = (tid & 7) << 3;           // bf16 col within 64
    const int l_row0 = tid >> 3;                 // 0..31
    const __nv_bfloat16* Ag = A + (size_t)(bm + l_row0) * K3 + l_c8;
    const __nv_bfloat16* Bg = B + (size_t)(bn + l_row0) * K3 + l_c8;
    const uint32_t s_sw = (uint32_t)((l_c8 * 2) ^ ((l_row0 & 7) << 4));
    // A rows l_row0+32i (i<4), B rows l_row0+32i (i<8); row*128 added at use.

    // ---- ldsm invariants ----------------------------------------------------
    const uint32_t lh16 = (uint32_t)(lane >> 4) << 4;
    uint32_t Ra[4], Rb[4];
    #pragma unroll
    for (int mt = 0; mt < 4; mt++) {
        const int r = wm * 64 + mt * 16 + (lane & 15);
        Ra[mt] = (uint32_t)(r * 128) + ((((uint32_t)r & 7) << 4) ^ lh16);
    }
    #pragma unroll
    for (int bt = 0; bt < 4; bt++) {
        const int r = wn * 64 + bt * 16 + (lane & 15);
        Rb[bt] = 16384u + (uint32_t)(r * 128) + ((((uint32_t)r & 7) << 4) ^ lh16);
    }

    float acc[4][8][4];
    #pragma unroll
    for (int i = 0; i < 4; i++)
        #pragma unroll
        for (int j = 0; j < 8; j++)
            #pragma unroll
            for (int k = 0; k < 4; k++) acc[i][j][k] = 0.f;

    auto load_stage = [&](int k0, uint32_t sstage) {
        #pragma unroll
        for (int i = 0; i < 4; i++) {
            const uint32_t so = (uint32_t)((l_row0 + 32 * i) * 128) + s_sw;
            cp_async16(sstage + so, Ag + (size_t)(32 * i) * K3 + k0);
        }
        #pragma unroll
        for (int i = 0; i < 8; i++) {
            const uint32_t so = (uint32_t)((l_row0 + 32 * i) * 128) + s_sw;
            cp_async16(sstage + 16384u + so, Bg + (size_t)(32 * i) * K3 + k0);
        }
    };

    const int S = K3 >> 6;
    load_stage(0,  sbase);               cp_commit();
    load_stage(64, sbase + STAGE_BYTES); cp_commit();

    uint32_t s_cur  = sbase;
    uint32_t s_next = sbase + 2 * STAGE_BYTES;
    for (int s = 0; s < S; s++) {
        cp_wait1();
        __syncthreads();

        if (s + 2 < S) load_stage((s + 2) << 6, s_next);
        cp_commit();
        s_next += STAGE_BYTES;
        if (s_next == sbase + 3 * STAGE_BYTES) s_next = sbase;

        #pragma unroll
        for (int ks = 0; ks < 4; ks++) {
            const uint32_t kx = (uint32_t)(ks * 32);
            uint32_t a[4][4];
            #pragma unroll
            for (int mt = 0; mt < 4; mt++)
                ldsm_x4(a[mt], (s_cur + Ra[mt]) ^ kx);
            uint32_t bfr[4][4];
            #pragma unroll
            for (int bt = 0; bt < 4; bt++)
                ldsm_x4(bfr[bt], (s_cur + Rb[bt]) ^ kx);
            #pragma unroll
            for (int mt = 0; mt < 4; mt++)
                #pragma unroll
                for (int nt = 0; nt < 8; nt++) {
                    const int bt = nt >> 1, wh = nt & 1;
                    mma16816(acc[mt][nt], a[mt], bfr[bt][wh], bfr[bt][wh + 2]);
                }
        }
        s_cur += STAGE_BYTES;
        if (s_cur == sbase + 3 * STAGE_BYTES) s_cur = sbase;
    }

    // epilogue
    const int colq = (lane & 3) * 2;
    const int rowq = lane >> 2;
    #pragma unroll
    for (int mt = 0; mt < 4; mt++) {
        #pragma unroll
        for (int nt = 0; nt < 8; nt++) {
            const int col = bn + wn * 64 + nt * 8 + colq;
            const float2 bz = *(const float2*)(bias + col);
            #pragma unroll
            for (int hh = 0; hh < 2; hh++) {
                const int grow = bm + wm * 64 + mt * 16 + rowq + hh * 8;
                float2 v;
                v.x = acc[mt][nt][hh * 2 + 0] + bz.x;
                v.y = acc[mt][nt][hh * 2 + 1] + bz.y;
                if (EPI == EPI_RES) {
                    const float2 r = *(const float2*)(res + (size_t)grow * N + col);
                    v.x += r.x; v.y += r.y;
                }
                if (EPI == EPI_GELU) {
                    v.x = gelu_exact(v.x); v.y = gelu_exact(v.y);
                }
                if (SPLIT_OUT) {
                    uint32_t hi, lo;
                    split_pair(v.x, v.y, hi, lo);
                    __nv_bfloat16* p = Cs + (size_t)grow * (3 * N) + col;
                    *(uint32_t*)(p)         = hi;
                    *(uint32_t*)(p + N)     = hi;
                    *(uint32_t*)(p + 2 * N) = lo;
                } else {
                    *(float2*)(C + (size_t)grow * N + col) = v;
                }
            }
        }
    }
}

// ---------------------------------------------------------------------------
// Launch
// ---------------------------------------------------------------------------
extern "C" void kernel_launch(void* const* d_in, const int* in_sizes, int n_in,
                              void* d_out, int out_size)
{
    const float* x      = (const float*)d_in[0];
    const float* qkv_w  = (const float*)d_in[1];
    const float* qkv_b  = (const float*)d_in[2];
    const float* proj_w = (const float*)d_in[3];
    const float* proj_b = (const float*)d_in[4];
    const float* ln1_w  = (const float*)d_in[5];
    const float* ln1_b  = (const float*)d_in[6];
    const float* ln2_w  = (const float*)d_in[7];
    const float* ln2_b  = (const float*)d_in[8];
    const float* mlp_w1 = (const float*)d_in[9];
    const float* mlp_b1 = (const float*)d_in[10];
    const float* mlp_w2 = (const float*)d_in[11];
    const float* mlp_b2 = (const float*)d_in[12];
    float* out = (float*)d_out;

    float *qkv, *x1;
    __nv_bfloat16 *act, *amlp, *wsq, *wsp, *ws1, *ws2;
    cudaGetSymbolAddress((void**)&qkv,  g_qkv);
    cudaGetSymbolAddress((void**)&x1,   g_x1);
    cudaGetSymbolAddress((void**)&act,  g_act);
    cudaGetSymbolAddress((void**)&amlp, g_amlp);
    cudaGetSymbolAddress((void**)&wsq,  g_ws_qkv);
    cudaGetSymbolAddress((void**)&wsp,  g_ws_proj);
    cudaGetSymbolAddress((void**)&ws1,  g_ws_w1);
    cudaGetSymbolAddress((void**)&ws2,  g_ws_w2);

    const int SMEM = STAGES * STAGE_BYTES;   // 144KB
    cudaFuncSetAttribute(gemm_mma<EPI_BIAS, false>, cudaFuncAttributeMaxDynamicSharedMemorySize, SMEM);
    cudaFuncSetAttribute(gemm_mma<EPI_RES,  false>, cudaFuncAttributeMaxDynamicSharedMemorySize, SMEM);
    cudaFuncSetAttribute(gemm_mma<EPI_GELU, true >, cudaFuncAttributeMaxDynamicSharedMemorySize, SMEM);

    const int M = M_ROWS;

    split_w_kernel<<<3072 * 1024 / 1024, 256>>>(qkv_w, wsq, 1024);
    ln_split_kernel<<<M, 256>>>(x, ln1_w, ln1_b, act);
    split_w_kernel<<<1024 * 1024 / 1024, 256>>>(proj_w, wsp, 1024);

    // launch slot 3: profiled
    gemm_mma<EPI_BIAS, false><<<dim3(3072 / 256, M / 128), 256, SMEM>>>(
        M, 3072, 3072, act, wsq, qkv_b, nullptr, qkv, nullptr);

    attn_split_kernel<<<M, 128>>>(qkv, act);

    gemm_mma<EPI_RES, false><<<dim3(1024 / 256, M / 128), 256, SMEM>>>(
        M, 1024, 3072, act, wsp, proj_b, x, x1, nullptr);

    ln_split_kernel<<<M, 256>>>(x1, ln2_w, ln2_b, act);
    split_w_kernel<<<4096 * 1024 / 1024, 256>>>(mlp_w1, ws1, 1024);

    gemm_mma<EPI_GELU, true><<<dim3(4096 / 256, M / 128), 256, SMEM>>>(
        M, 4096, 3072, act, ws1, mlp_b1, nullptr, nullptr, amlp);

    split_w_kernel<<<1024 * 4096 / 1024, 256>>>(mlp_w2, ws2, 4096);

    gemm_mma<EPI_RES, false><<<dim3(1024 / 256, M / 128), 256, SMEM>>>(
        M, 1024, 12288, amlp, ws2, mlp_b2, x1, out, nullptr);
}

// round 7
// speedup vs baseline: 1.2771x; 1.2771x over previous
#include <cuda_runtime.h>
#include <cuda_bf16.h>
#include <cstdint>
#include <math.h>

// ---------------------------------------------------------------------------
// SimpleTransformerBlock via warp-level bf16 mma.sync (sm_103 non-'a' PTX
// target: no tcgen05). fp32 accuracy via bf16 hi/lo split:
// A = [hi|hi|lo], B = [hi|lo|hi], K' = 3K.
// R7: R5 config restored (128x128 CTA, 32x64 warp tile, 16 warps/SM) +
//     compile-time N/K3 (folds address IMADs), unroll-1 stage loop.
// ---------------------------------------------------------------------------

#define M_ROWS 16384

// fp32 scratch
__device__ float g_qkv [(size_t)M_ROWS * 3072];
__device__ float g_x1  [(size_t)M_ROWS * 1024];
// bf16 split scratch
__device__ __nv_bfloat16 g_act  [(size_t)M_ROWS * 3072];     // A split, K=1024
__device__ __nv_bfloat16 g_amlp [(size_t)M_ROWS * 12288];    // A split, K=4096
__device__ __nv_bfloat16 g_ws_qkv [(size_t)3072 * 3072];
__device__ __nv_bfloat16 g_ws_proj[(size_t)1024 * 3072];
__device__ __nv_bfloat16 g_ws_w1  [(size_t)4096 * 3072];
__device__ __nv_bfloat16 g_ws_w2  [(size_t)1024 * 12288];

// ---------------------------------------------------------------------------
// PTX wrappers
// ---------------------------------------------------------------------------
__device__ __forceinline__ uint32_t smem_u32(const void* p) {
    uint32_t a;
    asm("{ .reg .u64 t; cvta.to.shared.u64 t, %1; cvt.u32.u64 %0, t; }" : "=r"(a) : "l"(p));
    return a;
}
__device__ __forceinline__ void cp_async16(uint32_t dst, const void* src) {
    asm volatile("cp.async.cg.shared.global [%0], [%1], 16;" :: "r"(dst), "l"(src));
}
__device__ __forceinline__ void cp_commit() {
    asm volatile("cp.async.commit_group;" ::: "memory");
}
__device__ __forceinline__ void cp_wait1() {
    asm volatile("cp.async.wait_group 1;" ::: "memory");
}
__device__ __forceinline__ void ldsm_x4(uint32_t* r, uint32_t addr) {
    asm volatile("ldmatrix.sync.aligned.m8n8.x4.shared.b16 {%0,%1,%2,%3}, [%4];"
                 : "=r"(r[0]), "=r"(r[1]), "=r"(r[2]), "=r"(r[3]) : "r"(addr));
}
__device__ __forceinline__ void mma16816(float* c, const uint32_t* a, uint32_t b0, uint32_t b1) {
    asm volatile(
        "mma.sync.aligned.m16n8k16.row.col.f32.bf16.bf16.f32 "
        "{%0,%1,%2,%3}, {%4,%5,%6,%7}, {%8,%9}, {%0,%1,%2,%3};"
        : "+f"(c[0]), "+f"(c[1]), "+f"(c[2]), "+f"(c[3])
        : "r"(a[0]), "r"(a[1]), "r"(a[2]), "r"(a[3]), "r"(b0), "r"(b1));
}
__device__ __forceinline__ uint32_t pack_bf16x2(float x, float y) {
    __nv_bfloat162 h = __floats2bfloat162_rn(x, y);
    return *(uint32_t*)&h;
}
__device__ __forceinline__ void split_pair(float x, float y, uint32_t& hi, uint32_t& lo) {
    __nv_bfloat16 hx = __float2bfloat16(x), hy = __float2bfloat16(y);
    hi = ((uint32_t)*(uint16_t*)&hy << 16) | *(uint16_t*)&hx;
    lo = pack_bf16x2(x - __bfloat162float(hx), y - __bfloat162float(hy));
}

// ---------------------------------------------------------------------------
// LayerNorm fused with hi/lo split: out row = [hi(1024) | hi(1024) | lo(1024)]
// ---------------------------------------------------------------------------
__global__ __launch_bounds__(256) void ln_split_kernel(
    const float* __restrict__ x, const float* __restrict__ w,
    const float* __restrict__ b, __nv_bfloat16* __restrict__ out)
{
    const int row = blockIdx.x;
    const int t   = threadIdx.x;
    const float4 v = ((const float4*)(x + (size_t)row * 1024))[t];
    float s  = v.x + v.y + v.z + v.w;
    float sq = v.x*v.x + v.y*v.y + v.z*v.z + v.w*v.w;
    #pragma unroll
    for (int o = 16; o > 0; o >>= 1) {
        s  += __shfl_xor_sync(0xffffffffu, s,  o);
        sq += __shfl_xor_sync(0xffffffffu, sq, o);
    }
    __shared__ float sm[8], sm2[8];
    const int warp = t >> 5, lane = t & 31;
    if (lane == 0) { sm[warp] = s; sm2[warp] = sq; }
    __syncthreads();
    if (t == 0) {
        float a = 0.f, c = 0.f;
        #pragma unroll
        for (int i = 0; i < 8; i++) { a += sm[i]; c += sm2[i]; }
        sm[0] = a; sm2[0] = c;
    }
    __syncthreads();
    const float mean = sm[0]  * (1.f / 1024.f);
    const float var  = sm2[0] * (1.f / 1024.f) - mean * mean;
    const float inv  = rsqrtf(var + 1e-5f);
    const float4 wv = ((const float4*)w)[t];
    const float4 bv = ((const float4*)b)[t];
    const float o0 = (v.x - mean) * inv * wv.x + bv.x;
    const float o1 = (v.y - mean) * inv * wv.y + bv.y;
    const float o2 = (v.z - mean) * inv * wv.z + bv.z;
    const float o3 = (v.w - mean) * inv * wv.w + bv.w;

    uint2 H, L;
    split_pair(o0, o1, H.x, L.x);
    split_pair(o2, o3, H.y, L.y);

    __nv_bfloat16* base = out + (size_t)row * 3072 + t * 4;
    *(uint2*)(base)        = H;
    *(uint2*)(base + 1024) = H;
    *(uint2*)(base + 2048) = L;
}

// ---------------------------------------------------------------------------
// fp32 -> bf16 hi/lo split for weights: [hi | lo | hi]
// ---------------------------------------------------------------------------
__global__ __launch_bounds__(256) void split_w_kernel(
    const float* __restrict__ in, __nv_bfloat16* __restrict__ out, int K)
{
    const size_t e = ((size_t)blockIdx.x * 256 + threadIdx.x) * 4;
    const size_t r = e / (size_t)K;
    const int    c = (int)(e - r * (size_t)K);
    const float4 v = *(const float4*)(in + e);

    uint2 H, L;
    split_pair(v.x, v.y, H.x, L.x);
    split_pair(v.z, v.w, H.y, L.y);

    __nv_bfloat16* base = out + r * (size_t)(3 * K) + c;
    *(uint2*)(base)         = H;
    *(uint2*)(base + K)     = L;
    *(uint2*)(base + 2 * K) = H;
}

// ---------------------------------------------------------------------------
// Per-position head-mix attention, float4 LDS, fused hi/lo split output.
// ---------------------------------------------------------------------------
__global__ __launch_bounds__(128) void attn_split_kernel(
    const float* __restrict__ qkv, __nv_bfloat16* __restrict__ out)
{
    const int pos = blockIdx.x;
    const int t   = threadIdx.x;
    const float4* base = (const float4*)(qkv + (size_t)pos * 3072);

    __shared__ float4 sq[256], sk[256], sv[256];
    __shared__ float S[16][17];

    sq[t]       = base[t];
    sq[t + 128] = base[t + 128];
    sk[t]       = base[256 + t];
    sk[t + 128] = base[256 + t + 128];
    sv[t]       = base[512 + t];
    sv[t + 128] = base[512 + t + 128];
    __syncthreads();

    #pragma unroll
    for (int ee = 0; ee < 2; ee++) {
        const int e = t + ee * 128;
        const int h = e >> 4, g = e & 15;
        float4 a = make_float4(0.f, 0.f, 0.f, 0.f);
        #pragma unroll
        for (int d4 = 0; d4 < 16; d4++) {
            const float4 qv = sq[h * 16 + d4];
            const float4 kv = sk[g * 16 + d4];
            a.x = fmaf(qv.x, kv.x, a.x);
            a.y = fmaf(qv.y, kv.y, a.y);
            a.z = fmaf(qv.z, kv.z, a.z);
            a.w = fmaf(qv.w, kv.w, a.w);
        }
        S[h][g] = (a.x + a.y + a.z + a.w) * 0.125f;
    }
    __syncthreads();

    if (t < 16) {
        float m = -1e30f;
        #pragma unroll
        for (int g = 0; g < 16; g++) m = fmaxf(m, S[t][g]);
        float sum = 0.f;
        #pragma unroll
        for (int g = 0; g < 16; g++) { float e = expf(S[t][g] - m); S[t][g] = e; sum += e; }
        const float inv = 1.f / sum;
        #pragma unroll
        for (int g = 0; g < 16; g++) S[t][g] *= inv;
    }
    __syncthreads();

    __nv_bfloat16* orow = out + (size_t)pos * 3072;
    #pragma unroll
    for (int qq = 0; qq < 2; qq++) {
        const int q  = t + qq * 128;
        const int h  = q >> 4, d4 = q & 15;
        float4 a = make_float4(0.f, 0.f, 0.f, 0.f);
        #pragma unroll
        for (int g = 0; g < 16; g++) {
            const float p = S[h][g];
            const float4 vv = sv[g * 16 + d4];
            a.x = fmaf(p, vv.x, a.x);
            a.y = fmaf(p, vv.y, a.y);
            a.z = fmaf(p, vv.z, a.z);
            a.w = fmaf(p, vv.w, a.w);
        }
        uint2 H, L;
        split_pair(a.x, a.y, H.x, L.x);
        split_pair(a.z, a.w, H.y, L.y);
        __nv_bfloat16* p0 = orow + q * 4;
        *(uint2*)(p0)        = H;
        *(uint2*)(p0 + 1024) = H;
        *(uint2*)(p0 + 2048) = L;
    }
}

// ---------------------------------------------------------------------------
// bf16 mma.sync GEMM: C = A[M,K3] @ B[N,K3]^T + bias (+res | +gelu[+split])
// BM=BN=128, BK=64, 256 thr (8 warps 4x2, warp tile 32x64), 3-stage cp.async.
// N and K3 are compile-time: all global address math folds to immediates.
// Swizzle identity: swz(r*128 + c*16) = r*128 + (c*16 ^ ((r&7)<<4)).
// ---------------------------------------------------------------------------
#define STAGES 3
#define STAGE_BYTES 32768

#define EPI_BIAS 0
#define EPI_RES  1
#define EPI_GELU 2

__device__ __forceinline__ float gelu_exact(float v) {
    return 0.5f * v * (1.0f + erff(v * 0.70710678118654752f));
}

template<int EPI, bool SPLIT_OUT, int N, int K3>
__global__ __launch_bounds__(256, 2) void gemm_mma(
    const __nv_bfloat16* __restrict__ A,   // [M, K3]
    const __nv_bfloat16* __restrict__ B,   // [N, K3]
    const float* __restrict__ bias,
    const float* __restrict__ res,
    float* __restrict__ C,
    __nv_bfloat16* __restrict__ Cs)        // split out [hi|hi|lo], stride 3N
{
    extern __shared__ char smem[];
    const uint32_t sbase = smem_u32(smem);

    const int tid  = threadIdx.x;
    const int wid  = tid >> 5;
    const int lane = tid & 31;
    const int wm   = wid & 3;
    const int wn   = wid >> 2;

    const int bm = blockIdx.y * 128;
    const int bn = blockIdx.x * 128;

    // ---- loader invariants: 4 chunks/operand/stage, 16B each -------------
    const int l_c8   = (tid & 7) << 3;           // bf16 col within 64
    const int l_row0 = tid >> 3;                 // rows row0 + 32*i
    const __nv_bfloat16* Ag = A + (size_t)(bm + l_row0) * K3 + l_c8;
    const __nv_bfloat16* Bg = B + (size_t)(bn + l_row0) * K3 + l_c8;
    const uint32_t s_sw = (uint32_t)((l_c8 * 2) ^ ((l_row0 & 7) << 4));

    // ---- ldsm invariants --------------------------------------------------
    const uint32_t lh16 = (uint32_t)(lane >> 4) << 4;   // 16B col select
    uint32_t Ra[2], Rb[4];
    #pragma unroll
    for (int mt = 0; mt < 2; mt++) {
        const int r = wm * 32 + mt * 16 + (lane & 15);
        Ra[mt] = (uint32_t)(r * 128) + ((((uint32_t)r & 7) << 4) ^ lh16);
    }
    #pragma unroll
    for (int bt = 0; bt < 4; bt++) {
        const int r = wn * 64 + bt * 16 + (lane & 15);
        Rb[bt] = 16384u + (uint32_t)(r * 128) + ((((uint32_t)r & 7) << 4) ^ lh16);
    }

    float acc[2][8][4];
    #pragma unroll
    for (int i = 0; i < 2; i++)
        #pragma unroll
        for (int j = 0; j < 8; j++)
            #pragma unroll
            for (int k = 0; k < 4; k++) acc[i][j][k] = 0.f;

    auto load_stage = [&](int k0, uint32_t sstage) {
        #pragma unroll
        for (int i = 0; i < 4; i++) {
            const uint32_t so = (uint32_t)((l_row0 + 32 * i) * 128) + s_sw;
            cp_async16(sstage + so,          Ag + (size_t)(32 * i) * K3 + k0);
            cp_async16(sstage + 16384u + so, Bg + (size_t)(32 * i) * K3 + k0);
        }
    };

    constexpr int S = K3 >> 6;
    load_stage(0,  sbase);               cp_commit();
    load_stage(64, sbase + STAGE_BYTES); cp_commit();

    uint32_t s_cur  = sbase;
    uint32_t s_next = sbase + 2 * STAGE_BYTES;
    #pragma unroll 1
    for (int s = 0; s < S; s++) {
        cp_wait1();
        __syncthreads();

        if (s + 2 < S) load_stage((s + 2) << 6, s_next);
        cp_commit();
        s_next += STAGE_BYTES;
        if (s_next == sbase + 3 * STAGE_BYTES) s_next = sbase;

        #pragma unroll
        for (int ks = 0; ks < 4; ks++) {
            const uint32_t kx = (uint32_t)(ks * 32);
            uint32_t a[2][4];
            #pragma unroll
            for (int mt = 0; mt < 2; mt++)
                ldsm_x4(a[mt], (s_cur + Ra[mt]) ^ kx);
            uint32_t bfr[4][4];
            #pragma unroll
            for (int bt = 0; bt < 4; bt++)
                ldsm_x4(bfr[bt], (s_cur + Rb[bt]) ^ kx);
            #pragma unroll
            for (int mt = 0; mt < 2; mt++)
                #pragma unroll
                for (int nt = 0; nt < 8; nt++) {
                    const int bt = nt >> 1, wh = nt & 1;
                    mma16816(acc[mt][nt], a[mt], bfr[bt][wh], bfr[bt][wh + 2]);
                }
        }
        s_cur += STAGE_BYTES;
        if (s_cur == sbase + 3 * STAGE_BYTES) s_cur = sbase;
    }

    // epilogue
    const int colq = (lane & 3) * 2;
    const int rowq = lane >> 2;
    #pragma unroll
    for (int mt = 0; mt < 2; mt++) {
        #pragma unroll
        for (int nt = 0; nt < 8; nt++) {
            const int col = bn + wn * 64 + nt * 8 + colq;
            const float2 bz = *(const float2*)(bias + col);
            #pragma unroll
            for (int hh = 0; hh < 2; hh++) {
                const int grow = bm + wm * 32 + mt * 16 + rowq + hh * 8;
                float2 v;
                v.x = acc[mt][nt][hh * 2 + 0] + bz.x;
                v.y = acc[mt][nt][hh * 2 + 1] + bz.y;
                if (EPI == EPI_RES) {
                    const float2 r = *(const float2*)(res + (size_t)grow * N + col);
                    v.x += r.x; v.y += r.y;
                }
                if (EPI == EPI_GELU) {
                    v.x = gelu_exact(v.x); v.y = gelu_exact(v.y);
                }
                if (SPLIT_OUT) {
                    uint32_t hi, lo;
                    split_pair(v.x, v.y, hi, lo);
                    __nv_bfloat16* p = Cs + (size_t)grow * (3 * N) + col;
                    *(uint32_t*)(p)         = hi;
                    *(uint32_t*)(p + N)     = hi;
                    *(uint32_t*)(p + 2 * N) = lo;
                } else {
                    *(float2*)(C + (size_t)grow * N + col) = v;
                }
            }
        }
    }
}

// ---------------------------------------------------------------------------
// Launch
// ---------------------------------------------------------------------------
extern "C" void kernel_launch(void* const* d_in, const int* in_sizes, int n_in,
                              void* d_out, int out_size)
{
    const float* x      = (const float*)d_in[0];
    const float* qkv_w  = (const float*)d_in[1];
    const float* qkv_b  = (const float*)d_in[2];
    const float* proj_w = (const float*)d_in[3];
    const float* proj_b = (const float*)d_in[4];
    const float* ln1_w  = (const float*)d_in[5];
    const float* ln1_b  = (const float*)d_in[6];
    const float* ln2_w  = (const float*)d_in[7];
    const float* ln2_b  = (const float*)d_in[8];
    const float* mlp_w1 = (const float*)d_in[9];
    const float* mlp_b1 = (const float*)d_in[10];
    const float* mlp_w2 = (const float*)d_in[11];
    const float* mlp_b2 = (const float*)d_in[12];
    float* out = (float*)d_out;

    float *qkv, *x1;
    __nv_bfloat16 *act, *amlp, *wsq, *wsp, *ws1, *ws2;
    cudaGetSymbolAddress((void**)&qkv,  g_qkv);
    cudaGetSymbolAddress((void**)&x1,   g_x1);
    cudaGetSymbolAddress((void**)&act,  g_act);
    cudaGetSymbolAddress((void**)&amlp, g_amlp);
    cudaGetSymbolAddress((void**)&wsq,  g_ws_qkv);
    cudaGetSymbolAddress((void**)&wsp,  g_ws_proj);
    cudaGetSymbolAddress((void**)&ws1,  g_ws_w1);
    cudaGetSymbolAddress((void**)&ws2,  g_ws_w2);

    const int SMEM = STAGES * STAGE_BYTES;   // 96KB
    cudaFuncSetAttribute((gemm_mma<EPI_BIAS, false, 3072, 3072>),  cudaFuncAttributeMaxDynamicSharedMemorySize, SMEM);
    cudaFuncSetAttribute((gemm_mma<EPI_RES,  false, 1024, 3072>),  cudaFuncAttributeMaxDynamicSharedMemorySize, SMEM);
    cudaFuncSetAttribute((gemm_mma<EPI_GELU, true,  4096, 3072>),  cudaFuncAttributeMaxDynamicSharedMemorySize, SMEM);
    cudaFuncSetAttribute((gemm_mma<EPI_RES,  false, 1024, 12288>), cudaFuncAttributeMaxDynamicSharedMemorySize, SMEM);

    const int M = M_ROWS;

    split_w_kernel<<<3072 * 1024 / 1024, 256>>>(qkv_w, wsq, 1024);
    ln_split_kernel<<<M, 256>>>(x, ln1_w, ln1_b, act);
    split_w_kernel<<<1024 * 1024 / 1024, 256>>>(proj_w, wsp, 1024);

    // launch slot 3: profiled
    gemm_mma<EPI_BIAS, false, 3072, 3072><<<dim3(3072 / 128, M / 128), 256, SMEM>>>(
        act, wsq, qkv_b, nullptr, qkv, nullptr);

    attn_split_kernel<<<M, 128>>>(qkv, act);

    gemm_mma<EPI_RES, false, 1024, 3072><<<dim3(1024 / 128, M / 128), 256, SMEM>>>(
        act, wsp, proj_b, x, x1, nullptr);

    ln_split_kernel<<<M, 256>>>(x1, ln2_w, ln2_b, act);
    split_w_kernel<<<4096 * 1024 / 1024, 256>>>(mlp_w1, ws1, 1024);

    gemm_mma<EPI_GELU, true, 4096, 3072><<<dim3(4096 / 128, M / 128), 256, SMEM>>>(
        act, ws1, mlp_b1, nullptr, nullptr, amlp);

    split_w_kernel<<<1024 * 4096 / 1024, 256>>>(mlp_w2, ws2, 4096);

    gemm_mma<EPI_RES, false, 1024, 12288><<<dim3(1024 / 128, M / 128), 256, SMEM>>>(
        amlp, ws2, mlp_b2, x1, out, nullptr);
}

// round 8
// speedup vs baseline: 1.8508x; 1.4492x over previous
#include <cuda_runtime.h>
#include <cuda_fp16.h>
#include <cstdint>
#include <math.h>

// ---------------------------------------------------------------------------
// SimpleTransformerBlock via warp-level fp16 mma.sync (sm_103 non-'a' PTX
// target: no tcgen05). fp32 accuracy via ONE-SIDED fp16 split (2 products):
//   A' = [fp16(a) | fp16(a)]          (activations, K'=2K)
//   B' = [fp16hi(b) | fp16lo(b)]      (weights,     K'=2K)
//   A'.B' = fp16(a) . (b_hi + b_lo) = fp16(a) . b   (error ~2^-12 from A)
// 33% less tensor work than the 3-product bf16 split of R5/R7.
// ---------------------------------------------------------------------------

#define M_ROWS 16384

// fp32 scratch
__device__ float g_qkv [(size_t)M_ROWS * 3072];
__device__ float g_x1  [(size_t)M_ROWS * 1024];
// fp16 split scratch
__device__ __half g_act  [(size_t)M_ROWS * 2048];     // A dup, K=1024
__device__ __half g_amlp [(size_t)M_ROWS * 8192];     // A dup, K=4096
__device__ __half g_ws_qkv [(size_t)3072 * 2048];
__device__ __half g_ws_proj[(size_t)1024 * 2048];
__device__ __half g_ws_w1  [(size_t)4096 * 2048];
__device__ __half g_ws_w2  [(size_t)1024 * 8192];

// ---------------------------------------------------------------------------
// PTX wrappers
// ---------------------------------------------------------------------------
__device__ __forceinline__ uint32_t smem_u32(const void* p) {
    uint32_t a;
    asm("{ .reg .u64 t; cvta.to.shared.u64 t, %1; cvt.u32.u64 %0, t; }" : "=r"(a) : "l"(p));
    return a;
}
__device__ __forceinline__ void cp_async16(uint32_t dst, const void* src) {
    asm volatile("cp.async.cg.shared.global [%0], [%1], 16;" :: "r"(dst), "l"(src));
}
__device__ __forceinline__ void cp_commit() {
    asm volatile("cp.async.commit_group;" ::: "memory");
}
__device__ __forceinline__ void cp_wait1() {
    asm volatile("cp.async.wait_group 1;" ::: "memory");
}
__device__ __forceinline__ void ldsm_x4(uint32_t* r, uint32_t addr) {
    asm volatile("ldmatrix.sync.aligned.m8n8.x4.shared.b16 {%0,%1,%2,%3}, [%4];"
                 : "=r"(r[0]), "=r"(r[1]), "=r"(r[2]), "=r"(r[3]) : "r"(addr));
}
__device__ __forceinline__ void mma16816(float* c, const uint32_t* a, uint32_t b0, uint32_t b1) {
    asm volatile(
        "mma.sync.aligned.m16n8k16.row.col.f32.f16.f16.f32 "
        "{%0,%1,%2,%3}, {%4,%5,%6,%7}, {%8,%9}, {%0,%1,%2,%3};"
        : "+f"(c[0]), "+f"(c[1]), "+f"(c[2]), "+f"(c[3])
        : "r"(a[0]), "r"(a[1]), "r"(a[2]), "r"(a[3]), "r"(b0), "r"(b1));
}
__device__ __forceinline__ uint32_t pack_h2(float x, float y) {
    __half2 h = __floats2half2_rn(x, y);
    return *(uint32_t*)&h;
}
// weight split: hi = fp16(x), lo = fp16(x - hi)
__device__ __forceinline__ void split_pair_w(float x, float y, uint32_t& hi, uint32_t& lo) {
    __half hx = __float2half_rn(x), hy = __float2half_rn(y);
    hi = ((uint32_t)*(uint16_t*)&hy << 16) | *(uint16_t*)&hx;
    lo = pack_h2(x - __half2float(hx), y - __half2float(hy));
}

// ---------------------------------------------------------------------------
// LayerNorm fused with fp16 duplicate store: out row = [h(1024) | h(1024)]
// ---------------------------------------------------------------------------
__global__ __launch_bounds__(256) void ln_split_kernel(
    const float* __restrict__ x, const float* __restrict__ w,
    const float* __restrict__ b, __half* __restrict__ out)
{
    const int row = blockIdx.x;
    const int t   = threadIdx.x;
    const float4 v = ((const float4*)(x + (size_t)row * 1024))[t];
    float s  = v.x + v.y + v.z + v.w;
    float sq = v.x*v.x + v.y*v.y + v.z*v.z + v.w*v.w;
    #pragma unroll
    for (int o = 16; o > 0; o >>= 1) {
        s  += __shfl_xor_sync(0xffffffffu, s,  o);
        sq += __shfl_xor_sync(0xffffffffu, sq, o);
    }
    __shared__ float sm[8], sm2[8];
    const int warp = t >> 5, lane = t & 31;
    if (lane == 0) { sm[warp] = s; sm2[warp] = sq; }
    __syncthreads();
    if (t == 0) {
        float a = 0.f, c = 0.f;
        #pragma unroll
        for (int i = 0; i < 8; i++) { a += sm[i]; c += sm2[i]; }
        sm[0] = a; sm2[0] = c;
    }
    __syncthreads();
    const float mean = sm[0]  * (1.f / 1024.f);
    const float var  = sm2[0] * (1.f / 1024.f) - mean * mean;
    const float inv  = rsqrtf(var + 1e-5f);
    const float4 wv = ((const float4*)w)[t];
    const float4 bv = ((const float4*)b)[t];
    const float o0 = (v.x - mean) * inv * wv.x + bv.x;
    const float o1 = (v.y - mean) * inv * wv.y + bv.y;
    const float o2 = (v.z - mean) * inv * wv.z + bv.z;
    const float o3 = (v.w - mean) * inv * wv.w + bv.w;

    uint2 H;
    H.x = pack_h2(o0, o1);
    H.y = pack_h2(o2, o3);

    __half* base = out + (size_t)row * 2048 + t * 4;
    *(uint2*)(base)        = H;
    *(uint2*)(base + 1024) = H;
}

// ---------------------------------------------------------------------------
// fp32 -> fp16 hi/lo split for weights: [hi | lo], row width 2K
// ---------------------------------------------------------------------------
__global__ __launch_bounds__(256) void split_w_kernel(
    const float* __restrict__ in, __half* __restrict__ out, int K)
{
    const size_t e = ((size_t)blockIdx.x * 256 + threadIdx.x) * 4;
    const size_t r = e / (size_t)K;
    const int    c = (int)(e - r * (size_t)K);
    const float4 v = *(const float4*)(in + e);

    uint2 H, L;
    split_pair_w(v.x, v.y, H.x, L.x);
    split_pair_w(v.z, v.w, H.y, L.y);

    __half* base = out + r * (size_t)(2 * K) + c;
    *(uint2*)(base)     = H;
    *(uint2*)(base + K) = L;
}

// ---------------------------------------------------------------------------
// Per-position head-mix attention, float4 LDS, fused fp16 duplicate output.
// ---------------------------------------------------------------------------
__global__ __launch_bounds__(128) void attn_split_kernel(
    const float* __restrict__ qkv, __half* __restrict__ out)
{
    const int pos = blockIdx.x;
    const int t   = threadIdx.x;
    const float4* base = (const float4*)(qkv + (size_t)pos * 3072);

    __shared__ float4 sq[256], sk[256], sv[256];
    __shared__ float S[16][17];

    sq[t]       = base[t];
    sq[t + 128] = base[t + 128];
    sk[t]       = base[256 + t];
    sk[t + 128] = base[256 + t + 128];
    sv[t]       = base[512 + t];
    sv[t + 128] = base[512 + t + 128];
    __syncthreads();

    #pragma unroll
    for (int ee = 0; ee < 2; ee++) {
        const int e = t + ee * 128;
        const int h = e >> 4, g = e & 15;
        float4 a = make_float4(0.f, 0.f, 0.f, 0.f);
        #pragma unroll
        for (int d4 = 0; d4 < 16; d4++) {
            const float4 qv = sq[h * 16 + d4];
            const float4 kv = sk[g * 16 + d4];
            a.x = fmaf(qv.x, kv.x, a.x);
            a.y = fmaf(qv.y, kv.y, a.y);
            a.z = fmaf(qv.z, kv.z, a.z);
            a.w = fmaf(qv.w, kv.w, a.w);
        }
        S[h][g] = (a.x + a.y + a.z + a.w) * 0.125f;
    }
    __syncthreads();

    if (t < 16) {
        float m = -1e30f;
        #pragma unroll
        for (int g = 0; g < 16; g++) m = fmaxf(m, S[t][g]);
        float sum = 0.f;
        #pragma unroll
        for (int g = 0; g < 16; g++) { float e = expf(S[t][g] - m); S[t][g] = e; sum += e; }
        const float inv = 1.f / sum;
        #pragma unroll
        for (int g = 0; g < 16; g++) S[t][g] *= inv;
    }
    __syncthreads();

    __half* orow = out + (size_t)pos * 2048;
    #pragma unroll
    for (int qq = 0; qq < 2; qq++) {
        const int q  = t + qq * 128;
        const int h  = q >> 4, d4 = q & 15;
        float4 a = make_float4(0.f, 0.f, 0.f, 0.f);
        #pragma unroll
        for (int g = 0; g < 16; g++) {
            const float p = S[h][g];
            const float4 vv = sv[g * 16 + d4];
            a.x = fmaf(p, vv.x, a.x);
            a.y = fmaf(p, vv.y, a.y);
            a.z = fmaf(p, vv.z, a.z);
            a.w = fmaf(p, vv.w, a.w);
        }
        uint2 H;
        H.x = pack_h2(a.x, a.y);
        H.y = pack_h2(a.z, a.w);
        __half* p0 = orow + q * 4;
        *(uint2*)(p0)        = H;
        *(uint2*)(p0 + 1024) = H;
    }
}

// ---------------------------------------------------------------------------
// fp16 mma.sync GEMM: C = A[M,KK] @ B[N,KK]^T + bias (+res | +gelu[+dup])
// BM=BN=128, BK=64, 256 thr (8 warps 4x2, warp tile 32x64), 3-stage cp.async.
// Swizzle identity: swz(r*128 + c*16) = r*128 + (c*16 ^ ((r&7)<<4)).
// ---------------------------------------------------------------------------
#define STAGES 3
#define STAGE_BYTES 32768

#define EPI_BIAS 0
#define EPI_RES  1
#define EPI_GELU 2

__device__ __forceinline__ float gelu_exact(float v) {
    return 0.5f * v * (1.0f + erff(v * 0.70710678118654752f));
}

template<int EPI, bool SPLIT_OUT, int N, int KK>
__global__ __launch_bounds__(256, 2) void gemm_mma(
    const __half* __restrict__ A,   // [M, KK]
    const __half* __restrict__ B,   // [N, KK]
    const float* __restrict__ bias,
    const float* __restrict__ res,
    float* __restrict__ C,
    __half* __restrict__ Cs)        // dup out [h|h], stride 2N
{
    extern __shared__ char smem[];
    const uint32_t sbase = smem_u32(smem);

    const int tid  = threadIdx.x;
    const int wid  = tid >> 5;
    const int lane = tid & 31;
    const int wm   = wid & 3;
    const int wn   = wid >> 2;

    const int bm = blockIdx.y * 128;
    const int bn = blockIdx.x * 128;

    // ---- loader invariants: 4 chunks/operand/stage, 16B each -------------
    const int l_c8   = (tid & 7) << 3;           // fp16 col within 64
    const int l_row0 = tid >> 3;                 // rows row0 + 32*i
    const __half* Ag = A + (size_t)(bm + l_row0) * KK + l_c8;
    const __half* Bg = B + (size_t)(bn + l_row0) * KK + l_c8;
    const uint32_t s_sw = (uint32_t)((l_c8 * 2) ^ ((l_row0 & 7) << 4));

    // ---- ldsm invariants --------------------------------------------------
    const uint32_t lh16 = (uint32_t)(lane >> 4) << 4;   // 16B col select
    uint32_t Ra[2], Rb[4];
    #pragma unroll
    for (int mt = 0; mt < 2; mt++) {
        const int r = wm * 32 + mt * 16 + (lane & 15);
        Ra[mt] = (uint32_t)(r * 128) + ((((uint32_t)r & 7) << 4) ^ lh16);
    }
    #pragma unroll
    for (int bt = 0; bt < 4; bt++) {
        const int r = wn * 64 + bt * 16 + (lane & 15);
        Rb[bt] = 16384u + (uint32_t)(r * 128) + ((((uint32_t)r & 7) << 4) ^ lh16);
    }

    float acc[2][8][4];
    #pragma unroll
    for (int i = 0; i < 2; i++)
        #pragma unroll
        for (int j = 0; j < 8; j++)
            #pragma unroll
            for (int k = 0; k < 4; k++) acc[i][j][k] = 0.f;

    auto load_stage = [&](int k0, uint32_t sstage) {
        #pragma unroll
        for (int i = 0; i < 4; i++) {
            const uint32_t so = (uint32_t)((l_row0 + 32 * i) * 128) + s_sw;
            cp_async16(sstage + so,          Ag + (size_t)(32 * i) * KK + k0);
            cp_async16(sstage + 16384u + so, Bg + (size_t)(32 * i) * KK + k0);
        }
    };

    constexpr int S = KK >> 6;
    load_stage(0,  sbase);               cp_commit();
    load_stage(64, sbase + STAGE_BYTES); cp_commit();

    uint32_t s_cur  = sbase;
    uint32_t s_next = sbase + 2 * STAGE_BYTES;
    #pragma unroll 1
    for (int s = 0; s < S; s++) {
        cp_wait1();
        __syncthreads();

        if (s + 2 < S) load_stage((s + 2) << 6, s_next);
        cp_commit();
        s_next += STAGE_BYTES;
        if (s_next == sbase + 3 * STAGE_BYTES) s_next = sbase;

        #pragma unroll
        for (int ks = 0; ks < 4; ks++) {
            const uint32_t kx = (uint32_t)(ks * 32);
            uint32_t a[2][4];
            #pragma unroll
            for (int mt = 0; mt < 2; mt++)
                ldsm_x4(a[mt], (s_cur + Ra[mt]) ^ kx);
            uint32_t bfr[4][4];
            #pragma unroll
            for (int bt = 0; bt < 4; bt++)
                ldsm_x4(bfr[bt], (s_cur + Rb[bt]) ^ kx);
            #pragma unroll
            for (int mt = 0; mt < 2; mt++)
                #pragma unroll
                for (int nt = 0; nt < 8; nt++) {
                    const int bt = nt >> 1, wh = nt & 1;
                    mma16816(acc[mt][nt], a[mt], bfr[bt][wh], bfr[bt][wh + 2]);
                }
        }
        s_cur += STAGE_BYTES;
        if (s_cur == sbase + 3 * STAGE_BYTES) s_cur = sbase;
    }

    // epilogue
    const int colq = (lane & 3) * 2;
    const int rowq = lane >> 2;
    #pragma unroll
    for (int mt = 0; mt < 2; mt++) {
        #pragma unroll
        for (int nt = 0; nt < 8; nt++) {
            const int col = bn + wn * 64 + nt * 8 + colq;
            const float2 bz = *(const float2*)(bias + col);
            #pragma unroll
            for (int hh = 0; hh < 2; hh++) {
                const int grow = bm + wm * 32 + mt * 16 + rowq + hh * 8;
                float2 v;
                v.x = acc[mt][nt][hh * 2 + 0] + bz.x;
                v.y = acc[mt][nt][hh * 2 + 1] + bz.y;
                if (EPI == EPI_RES) {
                    const float2 r = *(const float2*)(res + (size_t)grow * N + col);
                    v.x += r.x; v.y += r.y;
                }
                if (EPI == EPI_GELU) {
                    v.x = gelu_exact(v.x); v.y = gelu_exact(v.y);
                }
                if (SPLIT_OUT) {
                    const uint32_t h2 = pack_h2(v.x, v.y);
                    __half* p = Cs + (size_t)grow * (2 * N) + col;
                    *(uint32_t*)(p)     = h2;
                    *(uint32_t*)(p + N) = h2;
                } else {
                    *(float2*)(C + (size_t)grow * N + col) = v;
                }
            }
        }
    }
}

// ---------------------------------------------------------------------------
// Launch
// ---------------------------------------------------------------------------
extern "C" void kernel_launch(void* const* d_in, const int* in_sizes, int n_in,
                              void* d_out, int out_size)
{
    const float* x      = (const float*)d_in[0];
    const float* qkv_w  = (const float*)d_in[1];
    const float* qkv_b  = (const float*)d_in[2];
    const float* proj_w = (const float*)d_in[3];
    const float* proj_b = (const float*)d_in[4];
    const float* ln1_w  = (const float*)d_in[5];
    const float* ln1_b  = (const float*)d_in[6];
    const float* ln2_w  = (const float*)d_in[7];
    const float* ln2_b  = (const float*)d_in[8];
    const float* mlp_w1 = (const float*)d_in[9];
    const float* mlp_b1 = (const float*)d_in[10];
    const float* mlp_w2 = (const float*)d_in[11];
    const float* mlp_b2 = (const float*)d_in[12];
    float* out = (float*)d_out;

    float *qkv, *x1;
    __half *act, *amlp, *wsq, *wsp, *ws1, *ws2;
    cudaGetSymbolAddress((void**)&qkv,  g_qkv);
    cudaGetSymbolAddress((void**)&x1,   g_x1);
    cudaGetSymbolAddress((void**)&act,  g_act);
    cudaGetSymbolAddress((void**)&amlp, g_amlp);
    cudaGetSymbolAddress((void**)&wsq,  g_ws_qkv);
    cudaGetSymbolAddress((void**)&wsp,  g_ws_proj);
    cudaGetSymbolAddress((void**)&ws1,  g_ws_w1);
    cudaGetSymbolAddress((void**)&ws2,  g_ws_w2);

    const int SMEM = STAGES * STAGE_BYTES;   // 96KB
    cudaFuncSetAttribute((gemm_mma<EPI_BIAS, false, 3072, 2048>), cudaFuncAttributeMaxDynamicSharedMemorySize, SMEM);
    cudaFuncSetAttribute((gemm_mma<EPI_RES,  false, 1024, 2048>), cudaFuncAttributeMaxDynamicSharedMemorySize, SMEM);
    cudaFuncSetAttribute((gemm_mma<EPI_GELU, true,  4096, 2048>), cudaFuncAttributeMaxDynamicSharedMemorySize, SMEM);
    cudaFuncSetAttribute((gemm_mma<EPI_RES,  false, 1024, 8192>), cudaFuncAttributeMaxDynamicSharedMemorySize, SMEM);

    const int M = M_ROWS;

    split_w_kernel<<<3072 * 1024 / 1024, 256>>>(qkv_w, wsq, 1024);
    ln_split_kernel<<<M, 256>>>(x, ln1_w, ln1_b, act);
    split_w_kernel<<<1024 * 1024 / 1024, 256>>>(proj_w, wsp, 1024);

    // launch slot 3: profiled
    gemm_mma<EPI_BIAS, false, 3072, 2048><<<dim3(3072 / 128, M / 128), 256, SMEM>>>(
        act, wsq, qkv_b, nullptr, qkv, nullptr);

    attn_split_kernel<<<M, 128>>>(qkv, act);

    gemm_mma<EPI_RES, false, 1024, 2048><<<dim3(1024 / 128, M / 128), 256, SMEM>>>(
        act, wsp, proj_b, x, x1, nullptr);

    ln_split_kernel<<<M, 256>>>(x1, ln2_w, ln2_b, act);
    split_w_kernel<<<4096 * 1024 / 1024, 256>>>(mlp_w1, ws1, 1024);

    gemm_mma<EPI_GELU, true, 4096, 2048><<<dim3(4096 / 128, M / 128), 256, SMEM>>>(
        act, ws1, mlp_b1, nullptr, nullptr, amlp);

    split_w_kernel<<<1024 * 4096 / 1024, 256>>>(mlp_w2, ws2, 4096);

    gemm_mma<EPI_RES, false, 1024, 8192><<<dim3(1024 / 128, M / 128), 256, SMEM>>>(
        amlp, ws2, mlp_b2, x1, out, nullptr);
}

// round 9
// speedup vs baseline: 3.2111x; 1.7349x over previous
#include <cuda_runtime.h>
#include <cuda_fp16.h>
#include <cstdint>
#include <math.h>

// ---------------------------------------------------------------------------
// SimpleTransformerBlock via warp-level fp16 mma.sync (sm_103 non-'a' PTX
// target: no tcgen05). R9: PLAIN fp16 GEMMs (K'=K).
// Error budget: fp16 rounding on A and W sides adds in quadrature;
// measured A-side-only rel_err was 1.37e-4 -> predicted ~2e-4 total (<1e-3).
// ---------------------------------------------------------------------------

#define M_ROWS 16384

// fp32 scratch
__device__ float g_qkv [(size_t)M_ROWS * 3072];
__device__ float g_x1  [(size_t)M_ROWS * 1024];
// fp16 scratch
__device__ __half g_act  [(size_t)M_ROWS * 1024];
__device__ __half g_amlp [(size_t)M_ROWS * 4096];
__device__ __half g_ws_qkv [(size_t)3072 * 1024];
__device__ __half g_ws_proj[(size_t)1024 * 1024];
__device__ __half g_ws_w1  [(size_t)4096 * 1024];
__device__ __half g_ws_w2  [(size_t)1024 * 4096];

// ---------------------------------------------------------------------------
// PTX wrappers
// ---------------------------------------------------------------------------
__device__ __forceinline__ uint32_t smem_u32(const void* p) {
    uint32_t a;
    asm("{ .reg .u64 t; cvta.to.shared.u64 t, %1; cvt.u32.u64 %0, t; }" : "=r"(a) : "l"(p));
    return a;
}
__device__ __forceinline__ void cp_async16(uint32_t dst, const void* src) {
    asm volatile("cp.async.cg.shared.global [%0], [%1], 16;" :: "r"(dst), "l"(src));
}
__device__ __forceinline__ void cp_commit() {
    asm volatile("cp.async.commit_group;" ::: "memory");
}
__device__ __forceinline__ void cp_wait1() {
    asm volatile("cp.async.wait_group 1;" ::: "memory");
}
__device__ __forceinline__ void ldsm_x4(uint32_t* r, uint32_t addr) {
    asm volatile("ldmatrix.sync.aligned.m8n8.x4.shared.b16 {%0,%1,%2,%3}, [%4];"
                 : "=r"(r[0]), "=r"(r[1]), "=r"(r[2]), "=r"(r[3]) : "r"(addr));
}
__device__ __forceinline__ void mma16816(float* c, const uint32_t* a, uint32_t b0, uint32_t b1) {
    asm volatile(
        "mma.sync.aligned.m16n8k16.row.col.f32.f16.f16.f32 "
        "{%0,%1,%2,%3}, {%4,%5,%6,%7}, {%8,%9}, {%0,%1,%2,%3};"
        : "+f"(c[0]), "+f"(c[1]), "+f"(c[2]), "+f"(c[3])
        : "r"(a[0]), "r"(a[1]), "r"(a[2]), "r"(a[3]), "r"(b0), "r"(b1));
}
__device__ __forceinline__ uint32_t pack_h2(float x, float y) {
    __half2 h = __floats2half2_rn(x, y);
    return *(uint32_t*)&h;
}

// ---------------------------------------------------------------------------
// LayerNorm -> fp16 store (row width 1024)
// ---------------------------------------------------------------------------
__global__ __launch_bounds__(256) void ln_h_kernel(
    const float* __restrict__ x, const float* __restrict__ w,
    const float* __restrict__ b, __half* __restrict__ out)
{
    const int row = blockIdx.x;
    const int t   = threadIdx.x;
    const float4 v = ((const float4*)(x + (size_t)row * 1024))[t];
    float s  = v.x + v.y + v.z + v.w;
    float sq = v.x*v.x + v.y*v.y + v.z*v.z + v.w*v.w;
    #pragma unroll
    for (int o = 16; o > 0; o >>= 1) {
        s  += __shfl_xor_sync(0xffffffffu, s,  o);
        sq += __shfl_xor_sync(0xffffffffu, sq, o);
    }
    __shared__ float sm[8], sm2[8];
    const int warp = t >> 5, lane = t & 31;
    if (lane == 0) { sm[warp] = s; sm2[warp] = sq; }
    __syncthreads();
    if (t == 0) {
        float a = 0.f, c = 0.f;
        #pragma unroll
        for (int i = 0; i < 8; i++) { a += sm[i]; c += sm2[i]; }
        sm[0] = a; sm2[0] = c;
    }
    __syncthreads();
    const float mean = sm[0]  * (1.f / 1024.f);
    const float var  = sm2[0] * (1.f / 1024.f) - mean * mean;
    const float inv  = rsqrtf(var + 1e-5f);
    const float4 wv = ((const float4*)w)[t];
    const float4 bv = ((const float4*)b)[t];
    uint2 H;
    H.x = pack_h2((v.x - mean) * inv * wv.x + bv.x, (v.y - mean) * inv * wv.y + bv.y);
    H.y = pack_h2((v.z - mean) * inv * wv.z + bv.z, (v.w - mean) * inv * wv.w + bv.w);
    *(uint2*)(out + (size_t)row * 1024 + t * 4) = H;
}

// ---------------------------------------------------------------------------
// fp32 -> fp16 convert (weights)
// ---------------------------------------------------------------------------
__global__ __launch_bounds__(256) void conv_w_kernel(
    const float* __restrict__ in, __half* __restrict__ out)
{
    const size_t e = ((size_t)blockIdx.x * 256 + threadIdx.x) * 4;
    const float4 v = *(const float4*)(in + e);
    uint2 H;
    H.x = pack_h2(v.x, v.y);
    H.y = pack_h2(v.z, v.w);
    *(uint2*)(out + e) = H;
}

// ---------------------------------------------------------------------------
// Per-position head-mix attention, float4 LDS, fp16 output (row width 1024).
// ---------------------------------------------------------------------------
__global__ __launch_bounds__(128) void attn_h_kernel(
    const float* __restrict__ qkv, __half* __restrict__ out)
{
    const int pos = blockIdx.x;
    const int t   = threadIdx.x;
    const float4* base = (const float4*)(qkv + (size_t)pos * 3072);

    __shared__ float4 sq[256], sk[256], sv[256];
    __shared__ float S[16][17];

    sq[t]       = base[t];
    sq[t + 128] = base[t + 128];
    sk[t]       = base[256 + t];
    sk[t + 128] = base[256 + t + 128];
    sv[t]       = base[512 + t];
    sv[t + 128] = base[512 + t + 128];
    __syncthreads();

    #pragma unroll
    for (int ee = 0; ee < 2; ee++) {
        const int e = t + ee * 128;
        const int h = e >> 4, g = e & 15;
        float4 a = make_float4(0.f, 0.f, 0.f, 0.f);
        #pragma unroll
        for (int d4 = 0; d4 < 16; d4++) {
            const float4 qv = sq[h * 16 + d4];
            const float4 kv = sk[g * 16 + d4];
            a.x = fmaf(qv.x, kv.x, a.x);
            a.y = fmaf(qv.y, kv.y, a.y);
            a.z = fmaf(qv.z, kv.z, a.z);
            a.w = fmaf(qv.w, kv.w, a.w);
        }
        S[h][g] = (a.x + a.y + a.z + a.w) * 0.125f;
    }
    __syncthreads();

    if (t < 16) {
        float m = -1e30f;
        #pragma unroll
        for (int g = 0; g < 16; g++) m = fmaxf(m, S[t][g]);
        float sum = 0.f;
        #pragma unroll
        for (int g = 0; g < 16; g++) { float e = expf(S[t][g] - m); S[t][g] = e; sum += e; }
        const float inv = 1.f / sum;
        #pragma unroll
        for (int g = 0; g < 16; g++) S[t][g] *= inv;
    }
    __syncthreads();

    __half* orow = out + (size_t)pos * 1024;
    #pragma unroll
    for (int qq = 0; qq < 2; qq++) {
        const int q  = t + qq * 128;
        const int h  = q >> 4, d4 = q & 15;
        float4 a = make_float4(0.f, 0.f, 0.f, 0.f);
        #pragma unroll
        for (int g = 0; g < 16; g++) {
            const float p = S[h][g];
            const float4 vv = sv[g * 16 + d4];
            a.x = fmaf(p, vv.x, a.x);
            a.y = fmaf(p, vv.y, a.y);
            a.z = fmaf(p, vv.z, a.z);
            a.w = fmaf(p, vv.w, a.w);
        }
        uint2 H;
        H.x = pack_h2(a.x, a.y);
        H.y = pack_h2(a.z, a.w);
        *(uint2*)(orow + q * 4) = H;
    }
}

// ---------------------------------------------------------------------------
// fp16 mma.sync GEMM: C = A[M,KK] @ B[N,KK]^T + bias (+res | +gelu[+h16 out])
// BM=BN=128, BK=64, 256 thr (8 warps 4x2, warp tile 32x64), 3-stage cp.async.
// Swizzle identity: swz(r*128 + c*16) = r*128 + (c*16 ^ ((r&7)<<4)).
// ---------------------------------------------------------------------------
#define STAGES 3
#define STAGE_BYTES 32768

#define EPI_BIAS 0
#define EPI_RES  1
#define EPI_GELU 2

__device__ __forceinline__ float gelu_exact(float v) {
    return 0.5f * v * (1.0f + erff(v * 0.70710678118654752f));
}

template<int EPI, bool H_OUT, int N, int KK>
__global__ __launch_bounds__(256, 2) void gemm_mma(
    const __half* __restrict__ A,   // [M, KK]
    const __half* __restrict__ B,   // [N, KK]
    const float* __restrict__ bias,
    const float* __restrict__ res,
    float* __restrict__ C,
    __half* __restrict__ Ch)        // fp16 out, stride N
{
    extern __shared__ char smem[];
    const uint32_t sbase = smem_u32(smem);

    const int tid  = threadIdx.x;
    const int wid  = tid >> 5;
    const int lane = tid & 31;
    const int wm   = wid & 3;
    const int wn   = wid >> 2;

    const int bm = blockIdx.y * 128;
    const int bn = blockIdx.x * 128;

    // ---- loader invariants: 4 chunks/operand/stage, 16B each -------------
    const int l_c8   = (tid & 7) << 3;           // fp16 col within 64
    const int l_row0 = tid >> 3;                 // rows row0 + 32*i
    const __half* Ag = A + (size_t)(bm + l_row0) * KK + l_c8;
    const __half* Bg = B + (size_t)(bn + l_row0) * KK + l_c8;
    const uint32_t s_sw = (uint32_t)((l_c8 * 2) ^ ((l_row0 & 7) << 4));

    // ---- ldsm invariants --------------------------------------------------
    const uint32_t lh16 = (uint32_t)(lane >> 4) << 4;   // 16B col select
    uint32_t Ra[2], Rb[4];
    #pragma unroll
    for (int mt = 0; mt < 2; mt++) {
        const int r = wm * 32 + mt * 16 + (lane & 15);
        Ra[mt] = (uint32_t)(r * 128) + ((((uint32_t)r & 7) << 4) ^ lh16);
    }
    #pragma unroll
    for (int bt = 0; bt < 4; bt++) {
        const int r = wn * 64 + bt * 16 + (lane & 15);
        Rb[bt] = 16384u + (uint32_t)(r * 128) + ((((uint32_t)r & 7) << 4) ^ lh16);
    }

    float acc[2][8][4];
    #pragma unroll
    for (int i = 0; i < 2; i++)
        #pragma unroll
        for (int j = 0; j < 8; j++)
            #pragma unroll
            for (int k = 0; k < 4; k++) acc[i][j][k] = 0.f;

    auto load_stage = [&](int k0, uint32_t sstage) {
        #pragma unroll
        for (int i = 0; i < 4; i++) {
            const uint32_t so = (uint32_t)((l_row0 + 32 * i) * 128) + s_sw;
            cp_async16(sstage + so,          Ag + (size_t)(32 * i) * KK + k0);
            cp_async16(sstage + 16384u + so, Bg + (size_t)(32 * i) * KK + k0);
        }
    };

    constexpr int S = KK >> 6;
    load_stage(0,  sbase);               cp_commit();
    load_stage(64, sbase + STAGE_BYTES); cp_commit();

    uint32_t s_cur  = sbase;
    uint32_t s_next = sbase + 2 * STAGE_BYTES;
    #pragma unroll 1
    for (int s = 0; s < S; s++) {
        cp_wait1();
        __syncthreads();

        if (s + 2 < S) load_stage((s + 2) << 6, s_next);
        cp_commit();
        s_next += STAGE_BYTES;
        if (s_next == sbase + 3 * STAGE_BYTES) s_next = sbase;

        #pragma unroll
        for (int ks = 0; ks < 4; ks++) {
            const uint32_t kx = (uint32_t)(ks * 32);
            uint32_t a[2][4];
            #pragma unroll
            for (int mt = 0; mt < 2; mt++)
                ldsm_x4(a[mt], (s_cur + Ra[mt]) ^ kx);
            uint32_t bfr[4][4];
            #pragma unroll
            for (int bt = 0; bt < 4; bt++)
                ldsm_x4(bfr[bt], (s_cur + Rb[bt]) ^ kx);
            #pragma unroll
            for (int mt = 0; mt < 2; mt++)
                #pragma unroll
                for (int nt = 0; nt < 8; nt++) {
                    const int bt = nt >> 1, wh = nt & 1;
                    mma16816(acc[mt][nt], a[mt], bfr[bt][wh], bfr[bt][wh + 2]);
                }
        }
        s_cur += STAGE_BYTES;
        if (s_cur == sbase + 3 * STAGE_BYTES) s_cur = sbase;
    }

    // epilogue
    const int colq = (lane & 3) * 2;
    const int rowq = lane >> 2;
    #pragma unroll
    for (int mt = 0; mt < 2; mt++) {
        #pragma unroll
        for (int nt = 0; nt < 8; nt++) {
            const int col = bn + wn * 64 + nt * 8 + colq;
            const float2 bz = *(const float2*)(bias + col);
            #pragma unroll
            for (int hh = 0; hh < 2; hh++) {
                const int grow = bm + wm * 32 + mt * 16 + rowq + hh * 8;
                float2 v;
                v.x = acc[mt][nt][hh * 2 + 0] + bz.x;
                v.y = acc[mt][nt][hh * 2 + 1] + bz.y;
                if (EPI == EPI_RES) {
                    const float2 r = *(const float2*)(res + (size_t)grow * N + col);
                    v.x += r.x; v.y += r.y;
                }
                if (EPI == EPI_GELU) {
                    v.x = gelu_exact(v.x); v.y = gelu_exact(v.y);
                }
                if (H_OUT) {
                    *(uint32_t*)(Ch + (size_t)grow * N + col) = pack_h2(v.x, v.y);
                } else {
                    *(float2*)(C + (size_t)grow * N + col) = v;
                }
            }
        }
    }
}

// ---------------------------------------------------------------------------
// Launch
// ---------------------------------------------------------------------------
extern "C" void kernel_launch(void* const* d_in, const int* in_sizes, int n_in,
                              void* d_out, int out_size)
{
    const float* x      = (const float*)d_in[0];
    const float* qkv_w  = (const float*)d_in[1];
    const float* qkv_b  = (const float*)d_in[2];
    const float* proj_w = (const float*)d_in[3];
    const float* proj_b = (const float*)d_in[4];
    const float* ln1_w  = (const float*)d_in[5];
    const float* ln1_b  = (const float*)d_in[6];
    const float* ln2_w  = (const float*)d_in[7];
    const float* ln2_b  = (const float*)d_in[8];
    const float* mlp_w1 = (const float*)d_in[9];
    const float* mlp_b1 = (const float*)d_in[10];
    const float* mlp_w2 = (const float*)d_in[11];
    const float* mlp_b2 = (const float*)d_in[12];
    float* out = (float*)d_out;

    float *qkv, *x1;
    __half *act, *amlp, *wsq, *wsp, *ws1, *ws2;
    cudaGetSymbolAddress((void**)&qkv,  g_qkv);
    cudaGetSymbolAddress((void**)&x1,   g_x1);
    cudaGetSymbolAddress((void**)&act,  g_act);
    cudaGetSymbolAddress((void**)&amlp, g_amlp);
    cudaGetSymbolAddress((void**)&wsq,  g_ws_qkv);
    cudaGetSymbolAddress((void**)&wsp,  g_ws_proj);
    cudaGetSymbolAddress((void**)&ws1,  g_ws_w1);
    cudaGetSymbolAddress((void**)&ws2,  g_ws_w2);

    const int SMEM = STAGES * STAGE_BYTES;   // 96KB
    cudaFuncSetAttribute((gemm_mma<EPI_BIAS, false, 3072, 1024>), cudaFuncAttributeMaxDynamicSharedMemorySize, SMEM);
    cudaFuncSetAttribute((gemm_mma<EPI_RES,  false, 1024, 1024>), cudaFuncAttributeMaxDynamicSharedMemorySize, SMEM);
    cudaFuncSetAttribute((gemm_mma<EPI_GELU, true,  4096, 1024>), cudaFuncAttributeMaxDynamicSharedMemorySize, SMEM);
    cudaFuncSetAttribute((gemm_mma<EPI_RES,  false, 1024, 4096>), cudaFuncAttributeMaxDynamicSharedMemorySize, SMEM);

    const int M = M_ROWS;

    conv_w_kernel<<<3072 * 1024 / 1024, 256>>>(qkv_w, wsq);
    ln_h_kernel<<<M, 256>>>(x, ln1_w, ln1_b, act);
    conv_w_kernel<<<1024 * 1024 / 1024, 256>>>(proj_w, wsp);

    // launch slot 3: profiled
    gemm_mma<EPI_BIAS, false, 3072, 1024><<<dim3(3072 / 128, M / 128), 256, SMEM>>>(
        act, wsq, qkv_b, nullptr, qkv, nullptr);

    attn_h_kernel<<<M, 128>>>(qkv, act);

    gemm_mma<EPI_RES, false, 1024, 1024><<<dim3(1024 / 128, M / 128), 256, SMEM>>>(
        act, wsp, proj_b, x, x1, nullptr);

    ln_h_kernel<<<M, 256>>>(x1, ln2_w, ln2_b, act);
    conv_w_kernel<<<4096 * 1024 / 1024, 256>>>(mlp_w1, ws1);

    gemm_mma<EPI_GELU, true, 4096, 1024><<<dim3(4096 / 128, M / 128), 256, SMEM>>>(
        act, ws1, mlp_b1, nullptr, nullptr, amlp);

    conv_w_kernel<<<1024 * 4096 / 1024, 256>>>(mlp_w2, ws2);

    gemm_mma<EPI_RES, false, 1024, 4096><<<dim3(1024 / 128, M / 128), 256, SMEM>>>(
        amlp, ws2, mlp_b2, x1, out, nullptr);
}

// round 10
// speedup vs baseline: 3.4646x; 1.0789x over previous
#include <cuda_runtime.h>
#include <cuda_fp16.h>
#include <cstdint>
#include <math.h>

// ---------------------------------------------------------------------------
// SimpleTransformerBlock via warp-level fp16 mma.sync (sm_103 non-'a' PTX
// target: no tcgen05). R10: fp16 qkv path, bank-conflict-free padded attn,
// non-volatile mma (scheduler freedom). GEMM pipeline = R9 known-good.
// ---------------------------------------------------------------------------

#define M_ROWS 16384

// fp32 scratch
__device__ float g_x1  [(size_t)M_ROWS * 1024];
// fp16 scratch
__device__ __half g_qkvh [(size_t)M_ROWS * 3072];
__device__ __half g_act  [(size_t)M_ROWS * 1024];
__device__ __half g_amlp [(size_t)M_ROWS * 4096];
__device__ __half g_ws_qkv [(size_t)3072 * 1024];
__device__ __half g_ws_proj[(size_t)1024 * 1024];
__device__ __half g_ws_w1  [(size_t)4096 * 1024];
__device__ __half g_ws_w2  [(size_t)1024 * 4096];

// ---------------------------------------------------------------------------
// PTX wrappers
// ---------------------------------------------------------------------------
__device__ __forceinline__ uint32_t smem_u32(const void* p) {
    uint32_t a;
    asm("{ .reg .u64 t; cvta.to.shared.u64 t, %1; cvt.u32.u64 %0, t; }" : "=r"(a) : "l"(p));
    return a;
}
__device__ __forceinline__ void cp_async16(uint32_t dst, const void* src) {
    asm volatile("cp.async.cg.shared.global [%0], [%1], 16;" :: "r"(dst), "l"(src));
}
__device__ __forceinline__ void cp_commit() {
    asm volatile("cp.async.commit_group;" ::: "memory");
}
__device__ __forceinline__ void cp_wait1() {
    asm volatile("cp.async.wait_group 1;" ::: "memory");
}
__device__ __forceinline__ void ldsm_x4(uint32_t* r, uint32_t addr) {
    asm volatile("ldmatrix.sync.aligned.m8n8.x4.shared.b16 {%0,%1,%2,%3}, [%4];"
                 : "=r"(r[0]), "=r"(r[1]), "=r"(r[2]), "=r"(r[3]) : "r"(addr));
}
// NOT volatile: pure register function of inputs -> ptxas may interleave
// HMMAs with the (volatile) ldsm stream to fill latency bubbles.
__device__ __forceinline__ void mma16816(float* c, const uint32_t* a, uint32_t b0, uint32_t b1) {
    asm("mma.sync.aligned.m16n8k16.row.col.f32.f16.f16.f32 "
        "{%0,%1,%2,%3}, {%4,%5,%6,%7}, {%8,%9}, {%0,%1,%2,%3};"
        : "+f"(c[0]), "+f"(c[1]), "+f"(c[2]), "+f"(c[3])
        : "r"(a[0]), "r"(a[1]), "r"(a[2]), "r"(a[3]), "r"(b0), "r"(b1));
}
__device__ __forceinline__ uint32_t pack_h2(float x, float y) {
    __half2 h = __floats2half2_rn(x, y);
    return *(uint32_t*)&h;
}

// ---------------------------------------------------------------------------
// LayerNorm -> fp16 store (row width 1024)
// ---------------------------------------------------------------------------
__global__ __launch_bounds__(256) void ln_h_kernel(
    const float* __restrict__ x, const float* __restrict__ w,
    const float* __restrict__ b, __half* __restrict__ out)
{
    const int row = blockIdx.x;
    const int t   = threadIdx.x;
    const float4 v = ((const float4*)(x + (size_t)row * 1024))[t];
    float s  = v.x + v.y + v.z + v.w;
    float sq = v.x*v.x + v.y*v.y + v.z*v.z + v.w*v.w;
    #pragma unroll
    for (int o = 16; o > 0; o >>= 1) {
        s  += __shfl_xor_sync(0xffffffffu, s,  o);
        sq += __shfl_xor_sync(0xffffffffu, sq, o);
    }
    __shared__ float sm[8], sm2[8];
    const int warp = t >> 5, lane = t & 31;
    if (lane == 0) { sm[warp] = s; sm2[warp] = sq; }
    __syncthreads();
    if (t == 0) {
        float a = 0.f, c = 0.f;
        #pragma unroll
        for (int i = 0; i < 8; i++) { a += sm[i]; c += sm2[i]; }
        sm[0] = a; sm2[0] = c;
    }
    __syncthreads();
    const float mean = sm[0]  * (1.f / 1024.f);
    const float var  = sm2[0] * (1.f / 1024.f) - mean * mean;
    const float inv  = rsqrtf(var + 1e-5f);
    const float4 wv = ((const float4*)w)[t];
    const float4 bv = ((const float4*)b)[t];
    uint2 H;
    H.x = pack_h2((v.x - mean) * inv * wv.x + bv.x, (v.y - mean) * inv * wv.y + bv.y);
    H.y = pack_h2((v.z - mean) * inv * wv.z + bv.z, (v.w - mean) * inv * wv.w + bv.w);
    *(uint2*)(out + (size_t)row * 1024 + t * 4) = H;
}

// ---------------------------------------------------------------------------
// fp32 -> fp16 convert (weights)
// ---------------------------------------------------------------------------
__global__ __launch_bounds__(256) void conv_w_kernel(
    const float* __restrict__ in, __half* __restrict__ out)
{
    const size_t e = ((size_t)blockIdx.x * 256 + threadIdx.x) * 4;
    const float4 v = *(const float4*)(in + e);
    uint2 H;
    H.x = pack_h2(v.x, v.y);
    H.y = pack_h2(v.z, v.w);
    *(uint2*)(out + e) = H;
}

// ---------------------------------------------------------------------------
// Per-position head-mix attention, fp16 in/out.
// smem rows padded to 68 halves (bank stride 34 words -> g-rows on distinct
// banks; 16-way conflicts of the unpadded layout eliminated).
// ---------------------------------------------------------------------------
#define ATT_PAD 68
__global__ __launch_bounds__(128) void attn_h_kernel(
    const __half* __restrict__ qkv, __half* __restrict__ out)
{
    const int pos = blockIdx.x;
    const int t   = threadIdx.x;
    const __half* base = qkv + (size_t)pos * 3072;

    __shared__ __half sQ[16 * ATT_PAD], sK[16 * ATT_PAD], sV[16 * ATT_PAD];
    __shared__ float S[16][17];

    // load 3072 halves, 6 uint2 chunks (4 halves) per thread, padded store
    #pragma unroll
    for (int i = 0; i < 6; i++) {
        const int chunk = t + i * 128;        // 0..767
        const int idx   = chunk * 4;          // half index 0..3068
        const uint2 d   = *(const uint2*)(base + idx);
        const int sec   = idx >> 10;          // 0=q 1=k 2=v
        const int rem   = idx & 1023;
        const int r     = rem >> 6;
        const int c     = rem & 63;
        __half* dst = (sec == 0 ? sQ : (sec == 1 ? sK : sV)) + r * ATT_PAD + c;
        *(uint2*)dst = d;
    }
    __syncthreads();

    // scores: 2 per thread
    #pragma unroll
    for (int ee = 0; ee < 2; ee++) {
        const int e = t + ee * 128;
        const int h = e >> 4, g = e & 15;
        const __half2* qh = (const __half2*)(sQ + h * ATT_PAD);
        const __half2* kh = (const __half2*)(sK + g * ATT_PAD);
        float acc = 0.f;
        #pragma unroll
        for (int d2 = 0; d2 < 32; d2++) {
            const float2 a = __half22float2(qh[d2]);
            const float2 b = __half22float2(kh[d2]);
            acc = fmaf(a.x, b.x, acc);
            acc = fmaf(a.y, b.y, acc);
        }
        S[h][g] = acc * 0.125f;
    }
    __syncthreads();

    if (t < 16) {
        float m = -1e30f;
        #pragma unroll
        for (int g = 0; g < 16; g++) m = fmaxf(m, S[t][g]);
        float sum = 0.f;
        #pragma unroll
        for (int g = 0; g < 16; g++) { float e = expf(S[t][g] - m); S[t][g] = e; sum += e; }
        const float inv = 1.f / sum;
        #pragma unroll
        for (int g = 0; g < 16; g++) S[t][g] *= inv;
    }
    __syncthreads();

    // out: 8 halves per thread
    const int h = t >> 3;
    const int d = (t & 7) * 8;
    float r[8];
    #pragma unroll
    for (int j = 0; j < 8; j++) r[j] = 0.f;
    #pragma unroll
    for (int g = 0; g < 16; g++) {
        const float p = S[h][g];
        const __half2* vh = (const __half2*)(sV + g * ATT_PAD + d);
        #pragma unroll
        for (int j = 0; j < 4; j++) {
            const float2 f = __half22float2(vh[j]);
            r[2 * j]     = fmaf(p, f.x, r[2 * j]);
            r[2 * j + 1] = fmaf(p, f.y, r[2 * j + 1]);
        }
    }
    uint4 o;
    o.x = pack_h2(r[0], r[1]);
    o.y = pack_h2(r[2], r[3]);
    o.z = pack_h2(r[4], r[5]);
    o.w = pack_h2(r[6], r[7]);
    *(uint4*)(out + (size_t)pos * 1024 + t * 8) = o;
}

// ---------------------------------------------------------------------------
// fp16 mma.sync GEMM: C = A[M,KK] @ B[N,KK]^T + bias (+res | +gelu; fp32 or
// fp16 out). BM=BN=128, BK=64, 256 thr (8 warps 4x2, warp tile 32x64),
// 3-stage cp.async. Swizzle: swz(r*128+c*16) = r*128 + (c*16 ^ ((r&7)<<4)).
// ---------------------------------------------------------------------------
#define STAGES 3
#define STAGE_BYTES 32768

#define EPI_BIAS 0
#define EPI_RES  1
#define EPI_GELU 2

__device__ __forceinline__ float gelu_exact(float v) {
    return 0.5f * v * (1.0f + erff(v * 0.70710678118654752f));
}

template<int EPI, bool H_OUT, int N, int KK>
__global__ __launch_bounds__(256, 2) void gemm_mma(
    const __half* __restrict__ A,   // [M, KK]
    const __half* __restrict__ B,   // [N, KK]
    const float* __restrict__ bias,
    const float* __restrict__ res,
    float* __restrict__ C,
    __half* __restrict__ Ch)        // fp16 out, stride N
{
    extern __shared__ char smem[];
    const uint32_t sbase = smem_u32(smem);

    const int tid  = threadIdx.x;
    const int wid  = tid >> 5;
    const int lane = tid & 31;
    const int wm   = wid & 3;
    const int wn   = wid >> 2;

    const int bm = blockIdx.y * 128;
    const int bn = blockIdx.x * 128;

    // ---- loader invariants: 4 chunks/operand/stage, 16B each -------------
    const int l_c8   = (tid & 7) << 3;
    const int l_row0 = tid >> 3;
    const __half* Ag = A + (size_t)(bm + l_row0) * KK + l_c8;
    const __half* Bg = B + (size_t)(bn + l_row0) * KK + l_c8;
    const uint32_t s_sw = (uint32_t)((l_c8 * 2) ^ ((l_row0 & 7) << 4));

    // ---- ldsm invariants --------------------------------------------------
    const uint32_t lh16 = (uint32_t)(lane >> 4) << 4;
    uint32_t Ra[2], Rb[4];
    #pragma unroll
    for (int mt = 0; mt < 2; mt++) {
        const int r = wm * 32 + mt * 16 + (lane & 15);
        Ra[mt] = (uint32_t)(r * 128) + ((((uint32_t)r & 7) << 4) ^ lh16);
    }
    #pragma unroll
    for (int bt = 0; bt < 4; bt++) {
        const int r = wn * 64 + bt * 16 + (lane & 15);
        Rb[bt] = 16384u + (uint32_t)(r * 128) + ((((uint32_t)r & 7) << 4) ^ lh16);
    }

    float acc[2][8][4];
    #pragma unroll
    for (int i = 0; i < 2; i++)
        #pragma unroll
        for (int j = 0; j < 8; j++)
            #pragma unroll
            for (int k = 0; k < 4; k++) acc[i][j][k] = 0.f;

    auto load_stage = [&](int k0, uint32_t sstage) {
        #pragma unroll
        for (int i = 0; i < 4; i++) {
            const uint32_t so = (uint32_t)((l_row0 + 32 * i) * 128) + s_sw;
            cp_async16(sstage + so,          Ag + (size_t)(32 * i) * KK + k0);
            cp_async16(sstage + 16384u + so, Bg + (size_t)(32 * i) * KK + k0);
        }
    };

    constexpr int S = KK >> 6;
    load_stage(0,  sbase);               cp_commit();
    load_stage(64, sbase + STAGE_BYTES); cp_commit();

    uint32_t s_cur  = sbase;
    uint32_t s_next = sbase + 2 * STAGE_BYTES;
    #pragma unroll 1
    for (int s = 0; s < S; s++) {
        cp_wait1();
        __syncthreads();

        if (s + 2 < S) load_stage((s + 2) << 6, s_next);
        cp_commit();
        s_next += STAGE_BYTES;
        if (s_next == sbase + 3 * STAGE_BYTES) s_next = sbase;

        #pragma unroll
        for (int ks = 0; ks < 4; ks++) {
            const uint32_t kx = (uint32_t)(ks * 32);
            uint32_t a[2][4];
            #pragma unroll
            for (int mt = 0; mt < 2; mt++)
                ldsm_x4(a[mt], (s_cur + Ra[mt]) ^ kx);
            uint32_t bfr[4][4];
            #pragma unroll
            for (int bt = 0; bt < 4; bt++)
                ldsm_x4(bfr[bt], (s_cur + Rb[bt]) ^ kx);
            #pragma unroll
            for (int mt = 0; mt < 2; mt++)
                #pragma unroll
                for (int nt = 0; nt < 8; nt++) {
                    const int bt = nt >> 1, wh = nt & 1;
                    mma16816(acc[mt][nt], a[mt], bfr[bt][wh], bfr[bt][wh + 2]);
                }
        }
        s_cur += STAGE_BYTES;
        if (s_cur == sbase + 3 * STAGE_BYTES) s_cur = sbase;
    }

    // epilogue
    const int colq = (lane & 3) * 2;
    const int rowq = lane >> 2;
    #pragma unroll
    for (int mt = 0; mt < 2; mt++) {
        #pragma unroll
        for (int nt = 0; nt < 8; nt++) {
            const int col = bn + wn * 64 + nt * 8 + colq;
            const float2 bz = *(const float2*)(bias + col);
            #pragma unroll
            for (int hh = 0; hh < 2; hh++) {
                const int grow = bm + wm * 32 + mt * 16 + rowq + hh * 8;
                float2 v;
                v.x = acc[mt][nt][hh * 2 + 0] + bz.x;
                v.y = acc[mt][nt][hh * 2 + 1] + bz.y;
                if (EPI == EPI_RES) {
                    const float2 r = *(const float2*)(res + (size_t)grow * N + col);
                    v.x += r.x; v.y += r.y;
                }
                if (EPI == EPI_GELU) {
                    v.x = gelu_exact(v.x); v.y = gelu_exact(v.y);
                }
                if (H_OUT) {
                    *(uint32_t*)(Ch + (size_t)grow * N + col) = pack_h2(v.x, v.y);
                } else {
                    *(float2*)(C + (size_t)grow * N + col) = v;
                }
            }
        }
    }
}

// ---------------------------------------------------------------------------
// Launch
// ---------------------------------------------------------------------------
extern "C" void kernel_launch(void* const* d_in, const int* in_sizes, int n_in,
                              void* d_out, int out_size)
{
    const float* x      = (const float*)d_in[0];
    const float* qkv_w  = (const float*)d_in[1];
    const float* qkv_b  = (const float*)d_in[2];
    const float* proj_w = (const float*)d_in[3];
    const float* proj_b = (const float*)d_in[4];
    const float* ln1_w  = (const float*)d_in[5];
    const float* ln1_b  = (const float*)d_in[6];
    const float* ln2_w  = (const float*)d_in[7];
    const float* ln2_b  = (const float*)d_in[8];
    const float* mlp_w1 = (const float*)d_in[9];
    const float* mlp_b1 = (const float*)d_in[10];
    const float* mlp_w2 = (const float*)d_in[11];
    const float* mlp_b2 = (const float*)d_in[12];
    float* out = (float*)d_out;

    float *x1;
    __half *qkvh, *act, *amlp, *wsq, *wsp, *ws1, *ws2;
    cudaGetSymbolAddress((void**)&x1,   g_x1);
    cudaGetSymbolAddress((void**)&qkvh, g_qkvh);
    cudaGetSymbolAddress((void**)&act,  g_act);
    cudaGetSymbolAddress((void**)&amlp, g_amlp);
    cudaGetSymbolAddress((void**)&wsq,  g_ws_qkv);
    cudaGetSymbolAddress((void**)&wsp,  g_ws_proj);
    cudaGetSymbolAddress((void**)&ws1,  g_ws_w1);
    cudaGetSymbolAddress((void**)&ws2,  g_ws_w2);

    const int SMEM = STAGES * STAGE_BYTES;   // 96KB
    cudaFuncSetAttribute((gemm_mma<EPI_BIAS, true,  3072, 1024>), cudaFuncAttributeMaxDynamicSharedMemorySize, SMEM);
    cudaFuncSetAttribute((gemm_mma<EPI_RES,  false, 1024, 1024>), cudaFuncAttributeMaxDynamicSharedMemorySize, SMEM);
    cudaFuncSetAttribute((gemm_mma<EPI_GELU, true,  4096, 1024>), cudaFuncAttributeMaxDynamicSharedMemorySize, SMEM);
    cudaFuncSetAttribute((gemm_mma<EPI_RES,  false, 1024, 4096>), cudaFuncAttributeMaxDynamicSharedMemorySize, SMEM);

    const int M = M_ROWS;

    conv_w_kernel<<<3072 * 1024 / 1024, 256>>>(qkv_w, wsq);
    ln_h_kernel<<<M, 256>>>(x, ln1_w, ln1_b, act);
    conv_w_kernel<<<1024 * 1024 / 1024, 256>>>(proj_w, wsp);

    // launch slot 3: profiled
    gemm_mma<EPI_BIAS, true, 3072, 1024><<<dim3(3072 / 128, M / 128), 256, SMEM>>>(
        act, wsq, qkv_b, nullptr, nullptr, qkvh);

    attn_h_kernel<<<M, 128>>>(qkvh, act);

    gemm_mma<EPI_RES, false, 1024, 1024><<<dim3(1024 / 128, M / 128), 256, SMEM>>>(
        act, wsp, proj_b, x, x1, nullptr);

    ln_h_kernel<<<M, 256>>>(x1, ln2_w, ln2_b, act);
    conv_w_kernel<<<4096 * 1024 / 1024, 256>>>(mlp_w1, ws1);

    gemm_mma<EPI_GELU, true, 4096, 1024><<<dim3(4096 / 128, M / 128), 256, SMEM>>>(
        act, ws1, mlp_b1, nullptr, nullptr, amlp);

    conv_w_kernel<<<1024 * 4096 / 1024, 256>>>(mlp_w2, ws2);

    gemm_mma<EPI_RES, false, 1024, 4096><<<dim3(1024 / 128, M / 128), 256, SMEM>>>(
        amlp, ws2, mlp_b2, x1, out, nullptr);
}

// round 11
// speedup vs baseline: 3.4696x; 1.0015x over previous
#include <cuda_runtime.h>
#include <cuda_fp16.h>
#include <cstdint>
#include <math.h>

// ---------------------------------------------------------------------------
// SimpleTransformerBlock via warp-level fp16 mma.sync (sm_103 non-'a' PTX
// target: no tcgen05). R11: explicit ks-level software pipelining in the GEMM
// mainloop (double-buffered A+B01 fragments, B23 covered by half1 MMAs).
// ---------------------------------------------------------------------------

#define M_ROWS 16384

// fp32 scratch
__device__ float g_x1  [(size_t)M_ROWS * 1024];
// fp16 scratch
__device__ __half g_qkvh [(size_t)M_ROWS * 3072];
__device__ __half g_act  [(size_t)M_ROWS * 1024];
__device__ __half g_amlp [(size_t)M_ROWS * 4096];
__device__ __half g_ws_qkv [(size_t)3072 * 1024];
__device__ __half g_ws_proj[(size_t)1024 * 1024];
__device__ __half g_ws_w1  [(size_t)4096 * 1024];
__device__ __half g_ws_w2  [(size_t)1024 * 4096];

// ---------------------------------------------------------------------------
// PTX wrappers
// ---------------------------------------------------------------------------
__device__ __forceinline__ uint32_t smem_u32(const void* p) {
    uint32_t a;
    asm("{ .reg .u64 t; cvta.to.shared.u64 t, %1; cvt.u32.u64 %0, t; }" : "=r"(a) : "l"(p));
    return a;
}
__device__ __forceinline__ void cp_async16(uint32_t dst, const void* src) {
    asm volatile("cp.async.cg.shared.global [%0], [%1], 16;" :: "r"(dst), "l"(src));
}
__device__ __forceinline__ void cp_commit() {
    asm volatile("cp.async.commit_group;" ::: "memory");
}
__device__ __forceinline__ void cp_wait1() {
    asm volatile("cp.async.wait_group 1;" ::: "memory");
}
__device__ __forceinline__ void ldsm_x4(uint32_t* r, uint32_t addr) {
    asm volatile("ldmatrix.sync.aligned.m8n8.x4.shared.b16 {%0,%1,%2,%3}, [%4];"
                 : "=r"(r[0]), "=r"(r[1]), "=r"(r[2]), "=r"(r[3]) : "r"(addr));
}
// non-volatile: pure register function -> ptxas schedules freely
__device__ __forceinline__ void mma16816(float* c, const uint32_t* a, uint32_t b0, uint32_t b1) {
    asm("mma.sync.aligned.m16n8k16.row.col.f32.f16.f16.f32 "
        "{%0,%1,%2,%3}, {%4,%5,%6,%7}, {%8,%9}, {%0,%1,%2,%3};"
        : "+f"(c[0]), "+f"(c[1]), "+f"(c[2]), "+f"(c[3])
        : "r"(a[0]), "r"(a[1]), "r"(a[2]), "r"(a[3]), "r"(b0), "r"(b1));
}
__device__ __forceinline__ uint32_t pack_h2(float x, float y) {
    __half2 h = __floats2half2_rn(x, y);
    return *(uint32_t*)&h;
}

// ---------------------------------------------------------------------------
// LayerNorm -> fp16 store (row width 1024)
// ---------------------------------------------------------------------------
__global__ __launch_bounds__(256) void ln_h_kernel(
    const float* __restrict__ x, const float* __restrict__ w,
    const float* __restrict__ b, __half* __restrict__ out)
{
    const int row = blockIdx.x;
    const int t   = threadIdx.x;
    const float4 v = ((const float4*)(x + (size_t)row * 1024))[t];
    float s  = v.x + v.y + v.z + v.w;
    float sq = v.x*v.x + v.y*v.y + v.z*v.z + v.w*v.w;
    #pragma unroll
    for (int o = 16; o > 0; o >>= 1) {
        s  += __shfl_xor_sync(0xffffffffu, s,  o);
        sq += __shfl_xor_sync(0xffffffffu, sq, o);
    }
    __shared__ float sm[8], sm2[8];
    const int warp = t >> 5, lane = t & 31;
    if (lane == 0) { sm[warp] = s; sm2[warp] = sq; }
    __syncthreads();
    if (t == 0) {
        float a = 0.f, c = 0.f;
        #pragma unroll
        for (int i = 0; i < 8; i++) { a += sm[i]; c += sm2[i]; }
        sm[0] = a; sm2[0] = c;
    }
    __syncthreads();
    const float mean = sm[0]  * (1.f / 1024.f);
    const float var  = sm2[0] * (1.f / 1024.f) - mean * mean;
    const float inv  = rsqrtf(var + 1e-5f);
    const float4 wv = ((const float4*)w)[t];
    const float4 bv = ((const float4*)b)[t];
    uint2 H;
    H.x = pack_h2((v.x - mean) * inv * wv.x + bv.x, (v.y - mean) * inv * wv.y + bv.y);
    H.y = pack_h2((v.z - mean) * inv * wv.z + bv.z, (v.w - mean) * inv * wv.w + bv.w);
    *(uint2*)(out + (size_t)row * 1024 + t * 4) = H;
}

// ---------------------------------------------------------------------------
// fp32 -> fp16 convert (weights)
// ---------------------------------------------------------------------------
__global__ __launch_bounds__(256) void conv_w_kernel(
    const float* __restrict__ in, __half* __restrict__ out)
{
    const size_t e = ((size_t)blockIdx.x * 256 + threadIdx.x) * 4;
    const float4 v = *(const float4*)(in + e);
    uint2 H;
    H.x = pack_h2(v.x, v.y);
    H.y = pack_h2(v.z, v.w);
    *(uint2*)(out + e) = H;
}

// ---------------------------------------------------------------------------
// Per-position head-mix attention, fp16 in/out, padded rows (no conflicts).
// ---------------------------------------------------------------------------
#define ATT_PAD 68
__global__ __launch_bounds__(128) void attn_h_kernel(
    const __half* __restrict__ qkv, __half* __restrict__ out)
{
    const int pos = blockIdx.x;
    const int t   = threadIdx.x;
    const __half* base = qkv + (size_t)pos * 3072;

    __shared__ __half sQ[16 * ATT_PAD], sK[16 * ATT_PAD], sV[16 * ATT_PAD];
    __shared__ float S[16][17];

    #pragma unroll
    for (int i = 0; i < 6; i++) {
        const int chunk = t + i * 128;
        const int idx   = chunk * 4;
        const uint2 d   = *(const uint2*)(base + idx);
        const int sec   = idx >> 10;
        const int rem   = idx & 1023;
        const int r     = rem >> 6;
        const int c     = rem & 63;
        __half* dst = (sec == 0 ? sQ : (sec == 1 ? sK : sV)) + r * ATT_PAD + c;
        *(uint2*)dst = d;
    }
    __syncthreads();

    #pragma unroll
    for (int ee = 0; ee < 2; ee++) {
        const int e = t + ee * 128;
        const int h = e >> 4, g = e & 15;
        const __half2* qh = (const __half2*)(sQ + h * ATT_PAD);
        const __half2* kh = (const __half2*)(sK + g * ATT_PAD);
        float acc = 0.f;
        #pragma unroll
        for (int d2 = 0; d2 < 32; d2++) {
            const float2 a = __half22float2(qh[d2]);
            const float2 b = __half22float2(kh[d2]);
            acc = fmaf(a.x, b.x, acc);
            acc = fmaf(a.y, b.y, acc);
        }
        S[h][g] = acc * 0.125f;
    }
    __syncthreads();

    if (t < 16) {
        float m = -1e30f;
        #pragma unroll
        for (int g = 0; g < 16; g++) m = fmaxf(m, S[t][g]);
        float sum = 0.f;
        #pragma unroll
        for (int g = 0; g < 16; g++) { float e = expf(S[t][g] - m); S[t][g] = e; sum += e; }
        const float inv = 1.f / sum;
        #pragma unroll
        for (int g = 0; g < 16; g++) S[t][g] *= inv;
    }
    __syncthreads();

    const int h = t >> 3;
    const int d = (t & 7) * 8;
    float r[8];
    #pragma unroll
    for (int j = 0; j < 8; j++) r[j] = 0.f;
    #pragma unroll
    for (int g = 0; g < 16; g++) {
        const float p = S[h][g];
        const __half2* vh = (const __half2*)(sV + g * ATT_PAD + d);
        #pragma unroll
        for (int j = 0; j < 4; j++) {
            const float2 f = __half22float2(vh[j]);
            r[2 * j]     = fmaf(p, f.x, r[2 * j]);
            r[2 * j + 1] = fmaf(p, f.y, r[2 * j + 1]);
        }
    }
    uint4 o;
    o.x = pack_h2(r[0], r[1]);
    o.y = pack_h2(r[2], r[3]);
    o.z = pack_h2(r[4], r[5]);
    o.w = pack_h2(r[6], r[7]);
    *(uint4*)(out + (size_t)pos * 1024 + t * 8) = o;
}

// ---------------------------------------------------------------------------
// fp16 mma.sync GEMM, software-pipelined fragments.
// BM=BN=128, BK=64, 256 thr (8 warps 4x2, warp tile 32x64), 3-stage cp.async.
// Per ks: [ldsm B23] [8 mma on A,B01] [ldsm A',B01' next ks] [8 mma on A,B23]
// Fragment regs: A 2x8 + B01 2x8 + B23 8 = 40; acc 64 -> ~122 total (<=128).
// ---------------------------------------------------------------------------
#define STAGES 3
#define STAGE_BYTES 32768

#define EPI_BIAS 0
#define EPI_RES  1
#define EPI_GELU 2

__device__ __forceinline__ float gelu_exact(float v) {
    return 0.5f * v * (1.0f + erff(v * 0.70710678118654752f));
}

template<int EPI, bool H_OUT, int N, int KK>
__global__ __launch_bounds__(256, 2) void gemm_mma(
    const __half* __restrict__ A,   // [M, KK]
    const __half* __restrict__ B,   // [N, KK]
    const float* __restrict__ bias,
    const float* __restrict__ res,
    float* __restrict__ C,
    __half* __restrict__ Ch)        // fp16 out, stride N
{
    extern __shared__ char smem[];
    const uint32_t sbase = smem_u32(smem);

    const int tid  = threadIdx.x;
    const int wid  = tid >> 5;
    const int lane = tid & 31;
    const int wm   = wid & 3;
    const int wn   = wid >> 2;

    const int bm = blockIdx.y * 128;
    const int bn = blockIdx.x * 128;

    // ---- loader invariants ------------------------------------------------
    const int l_c8   = (tid & 7) << 3;
    const int l_row0 = tid >> 3;
    const __half* Ag = A + (size_t)(bm + l_row0) * KK + l_c8;
    const __half* Bg = B + (size_t)(bn + l_row0) * KK + l_c8;
    const uint32_t s_sw = (uint32_t)((l_c8 * 2) ^ ((l_row0 & 7) << 4));

    // ---- ldsm invariants --------------------------------------------------
    const uint32_t lh16 = (uint32_t)(lane >> 4) << 4;
    uint32_t Ra[2], Rb[4];
    #pragma unroll
    for (int mt = 0; mt < 2; mt++) {
        const int r = wm * 32 + mt * 16 + (lane & 15);
        Ra[mt] = (uint32_t)(r * 128) + ((((uint32_t)r & 7) << 4) ^ lh16);
    }
    #pragma unroll
    for (int bt = 0; bt < 4; bt++) {
        const int r = wn * 64 + bt * 16 + (lane & 15);
        Rb[bt] = 16384u + (uint32_t)(r * 128) + ((((uint32_t)r & 7) << 4) ^ lh16);
    }

    float acc[2][8][4];
    #pragma unroll
    for (int i = 0; i < 2; i++)
        #pragma unroll
        for (int j = 0; j < 8; j++)
            #pragma unroll
            for (int k = 0; k < 4; k++) acc[i][j][k] = 0.f;

    auto load_stage = [&](int k0, uint32_t sstage) {
        #pragma unroll
        for (int i = 0; i < 4; i++) {
            const uint32_t so = (uint32_t)((l_row0 + 32 * i) * 128) + s_sw;
            cp_async16(sstage + so,          Ag + (size_t)(32 * i) * KK + k0);
            cp_async16(sstage + 16384u + so, Bg + (size_t)(32 * i) * KK + k0);
        }
    };

    constexpr int S = KK >> 6;
    load_stage(0,  sbase);               cp_commit();
    load_stage(64, sbase + STAGE_BYTES); cp_commit();

    uint32_t s_cur  = sbase;
    uint32_t s_next = sbase + 2 * STAGE_BYTES;

    uint32_t aF[2][2][4];   // [buf][mt][4]
    uint32_t bA[2][2][4];   // B01 [buf][bt][4]
    uint32_t bB[2][4];      // B23 current ks

    #pragma unroll 1
    for (int s = 0; s < S; s++) {
        cp_wait1();
        __syncthreads();

        if (s + 2 < S) load_stage((s + 2) << 6, s_next);
        cp_commit();
        s_next += STAGE_BYTES;
        if (s_next == sbase + 3 * STAGE_BYTES) s_next = sbase;

        // preload ks=0 fragments (A + B01)
        ldsm_x4(aF[0][0], s_cur + Ra[0]);
        ldsm_x4(aF[0][1], s_cur + Ra[1]);
        ldsm_x4(bA[0][0], s_cur + Rb[0]);
        ldsm_x4(bA[0][1], s_cur + Rb[1]);

        #pragma unroll
        for (int ks = 0; ks < 4; ks++) {
            const int cb = ks & 1, nb = cb ^ 1;
            const uint32_t kx = (uint32_t)(ks * 32);
            const uint32_t kn = (uint32_t)((ks + 1) * 32);

            // B23 for current ks
            ldsm_x4(bB[0], (s_cur + Rb[2]) ^ kx);
            ldsm_x4(bB[1], (s_cur + Rb[3]) ^ kx);

            // half1: nt 0..3 uses A + B01 (already resident)
            #pragma unroll
            for (int mt = 0; mt < 2; mt++)
                #pragma unroll
                for (int nt = 0; nt < 4; nt++) {
                    const int bt = nt >> 1, wh = nt & 1;
                    mma16816(acc[mt][nt], aF[cb][mt], bA[cb][bt][wh], bA[cb][bt][wh + 2]);
                }

            // prefetch next ks fragments (A + B01)
            if (ks < 3) {
                ldsm_x4(aF[nb][0], (s_cur + Ra[0]) ^ kn);
                ldsm_x4(aF[nb][1], (s_cur + Ra[1]) ^ kn);
                ldsm_x4(bA[nb][0], (s_cur + Rb[0]) ^ kn);
                ldsm_x4(bA[nb][1], (s_cur + Rb[1]) ^ kn);
            }

            // half2: nt 4..7 uses A + B23 (latency covered by half1 mmas)
            #pragma unroll
            for (int mt = 0; mt < 2; mt++)
                #pragma unroll
                for (int nt = 4; nt < 8; nt++) {
                    const int bt = (nt - 4) >> 1, wh = nt & 1;
                    mma16816(acc[mt][nt], aF[cb][mt], bB[bt][wh], bB[bt][wh + 2]);
                }
        }

        s_cur += STAGE_BYTES;
        if (s_cur == sbase + 3 * STAGE_BYTES) s_cur = sbase;
    }

    // epilogue
    const int colq = (lane & 3) * 2;
    const int rowq = lane >> 2;
    #pragma unroll
    for (int mt = 0; mt < 2; mt++) {
        #pragma unroll
        for (int nt = 0; nt < 8; nt++) {
            const int col = bn + wn * 64 + nt * 8 + colq;
            const float2 bz = *(const float2*)(bias + col);
            #pragma unroll
            for (int hh = 0; hh < 2; hh++) {
                const int grow = bm + wm * 32 + mt * 16 + rowq + hh * 8;
                float2 v;
                v.x = acc[mt][nt][hh * 2 + 0] + bz.x;
                v.y = acc[mt][nt][hh * 2 + 1] + bz.y;
                if (EPI == EPI_RES) {
                    const float2 r = *(const float2*)(res + (size_t)grow * N + col);
                    v.x += r.x; v.y += r.y;
                }
                if (EPI == EPI_GELU) {
                    v.x = gelu_exact(v.x); v.y = gelu_exact(v.y);
                }
                if (H_OUT) {
                    *(uint32_t*)(Ch + (size_t)grow * N + col) = pack_h2(v.x, v.y);
                } else {
                    *(float2*)(C + (size_t)grow * N + col) = v;
                }
            }
        }
    }
}

// ---------------------------------------------------------------------------
// Launch
// ---------------------------------------------------------------------------
extern "C" void kernel_launch(void* const* d_in, const int* in_sizes, int n_in,
                              void* d_out, int out_size)
{
    const float* x      = (const float*)d_in[0];
    const float* qkv_w  = (const float*)d_in[1];
    const float* qkv_b  = (const float*)d_in[2];
    const float* proj_w = (const float*)d_in[3];
    const float* proj_b = (const float*)d_in[4];
    const float* ln1_w  = (const float*)d_in[5];
    const float* ln1_b  = (const float*)d_in[6];
    const float* ln2_w  = (const float*)d_in[7];
    const float* ln2_b  = (const float*)d_in[8];
    const float* mlp_w1 = (const float*)d_in[9];
    const float* mlp_b1 = (const float*)d_in[10];
    const float* mlp_w2 = (const float*)d_in[11];
    const float* mlp_b2 = (const float*)d_in[12];
    float* out = (float*)d_out;

    float *x1;
    __half *qkvh, *act, *amlp, *wsq, *wsp, *ws1, *ws2;
    cudaGetSymbolAddress((void**)&x1,   g_x1);
    cudaGetSymbolAddress((void**)&qkvh, g_qkvh);
    cudaGetSymbolAddress((void**)&act,  g_act);
    cudaGetSymbolAddress((void**)&amlp, g_amlp);
    cudaGetSymbolAddress((void**)&wsq,  g_ws_qkv);
    cudaGetSymbolAddress((void**)&wsp,  g_ws_proj);
    cudaGetSymbolAddress((void**)&ws1,  g_ws_w1);
    cudaGetSymbolAddress((void**)&ws2,  g_ws_w2);

    const int SMEM = STAGES * STAGE_BYTES;   // 96KB
    cudaFuncSetAttribute((gemm_mma<EPI_BIAS, true,  3072, 1024>), cudaFuncAttributeMaxDynamicSharedMemorySize, SMEM);
    cudaFuncSetAttribute((gemm_mma<EPI_RES,  false, 1024, 1024>), cudaFuncAttributeMaxDynamicSharedMemorySize, SMEM);
    cudaFuncSetAttribute((gemm_mma<EPI_GELU, true,  4096, 1024>), cudaFuncAttributeMaxDynamicSharedMemorySize, SMEM);
    cudaFuncSetAttribute((gemm_mma<EPI_RES,  false, 1024, 4096>), cudaFuncAttributeMaxDynamicSharedMemorySize, SMEM);

    const int M = M_ROWS;

    conv_w_kernel<<<3072 * 1024 / 1024, 256>>>(qkv_w, wsq);
    ln_h_kernel<<<M, 256>>>(x, ln1_w, ln1_b, act);
    conv_w_kernel<<<1024 * 1024 / 1024, 256>>>(proj_w, wsp);

    // launch slot 3: profiled
    gemm_mma<EPI_BIAS, true, 3072, 1024><<<dim3(3072 / 128, M / 128), 256, SMEM>>>(
        act, wsq, qkv_b, nullptr, nullptr, qkvh);

    attn_h_kernel<<<M, 128>>>(qkvh, act);

    gemm_mma<EPI_RES, false, 1024, 1024><<<dim3(1024 / 128, M / 128), 256, SMEM>>>(
        act, wsp, proj_b, x, x1, nullptr);

    ln_h_kernel<<<M, 256>>>(x1, ln2_w, ln2_b, act);
    conv_w_kernel<<<4096 * 1024 / 1024, 256>>>(mlp_w1, ws1);

    gemm_mma<EPI_GELU, true, 4096, 1024><<<dim3(4096 / 128, M / 128), 256, SMEM>>>(
        act, ws1, mlp_b1, nullptr, nullptr, amlp);

    conv_w_kernel<<<1024 * 4096 / 1024, 256>>>(mlp_w2, ws2);

    gemm_mma<EPI_RES, false, 1024, 4096><<<dim3(1024 / 128, M / 128), 256, SMEM>>>(
        amlp, ws2, mlp_b2, x1, out, nullptr);
}